// round 6
// baseline (speedup 1.0000x reference)
#include <cuda_runtime.h>
#include <math_constants.h>

#define N_NODES 100000
#define N_EDGES 1600000
#define IN_F    128
#define OUT_F   128     // HEADS * D_K = 4 * 32

// ---------------- scratch (no allocations allowed) ----------------
__device__ float g_Q[N_NODES * OUT_F];
__device__ float g_K[N_NODES * OUT_F];
__device__ float g_V[N_NODES * OUT_F];
__device__ int   g_cnt[N_NODES];
__device__ int   g_off[N_NODES + 1];
__device__ int   g_cur[N_NODES];
__device__ int   g_src[N_EDGES];
__device__ int   g_is64;

// Edge accessor: ei is either int64[2, E] or int32[2, E]; g_is64 selects.
__device__ __forceinline__ int edge_at(const void* ei, int idx)
{
    if (g_is64) return (int)((const long long*)ei)[idx];
    return ((const int*)ei)[idx];
}

// Detect edge_index dtype from data: true int64 node ids are < N_NODES;
// int32 data reinterpreted as int64 packs two random ids -> huge values.
__global__ void k_detect(const void* __restrict__ ei)
{
    const long long* p = (const long long*)ei;
    bool ok = true;
    #pragma unroll
    for (int i = 0; i < 8; i++) {
        long long v = p[i];
        if (v < 0 || v >= N_NODES) ok = false;
    }
    g_is64 = ok ? 1 : 0;
}

// ---------------- QKV projection: out = x @ W^T -------------------
// Classic SGEMM, BM=BN=128, BK=16, 256 threads, 8x8 register tile.
__global__ __launch_bounds__(256) void qkv_gemm(
    const float* __restrict__ x,
    const float* __restrict__ Wq,
    const float* __restrict__ Wk,
    const float* __restrict__ Wv)
{
    const int BM = 128, BK = 16;
    __shared__ float As[BK][132];
    __shared__ float Bs[BK][132];

    const float* W;
    float* O;
    if (blockIdx.y == 0)      { W = Wq; O = g_Q; }
    else if (blockIdx.y == 1) { W = Wk; O = g_K; }
    else                      { W = Wv; O = g_V; }

    const int m0  = blockIdx.x * BM;
    const int tid = threadIdx.x;

    const int l_r = tid >> 2;          // 0..63 (rows l_r and l_r+64)
    const int l_c = (tid & 3) << 2;    // 0,4,8,12

    const int ty = tid >> 4;           // 0..15
    const int tx = tid & 15;           // 0..15

    float acc[8][8];
    #pragma unroll
    for (int i = 0; i < 8; i++)
        #pragma unroll
        for (int j = 0; j < 8; j++) acc[i][j] = 0.f;

    for (int kk = 0; kk < IN_F; kk += BK) {
        #pragma unroll
        for (int h = 0; h < 2; h++) {
            int row = l_r + h * 64;
            int gr  = m0 + row;
            float4 a = make_float4(0.f, 0.f, 0.f, 0.f);
            if (gr < N_NODES)
                a = *(const float4*)&x[gr * IN_F + kk + l_c];
            As[l_c + 0][row] = a.x;
            As[l_c + 1][row] = a.y;
            As[l_c + 2][row] = a.z;
            As[l_c + 3][row] = a.w;
        }
        #pragma unroll
        for (int h = 0; h < 2; h++) {
            int row = l_r + h * 64;
            float4 b = *(const float4*)&W[row * IN_F + kk + l_c];
            Bs[l_c + 0][row] = b.x;
            Bs[l_c + 1][row] = b.y;
            Bs[l_c + 2][row] = b.z;
            Bs[l_c + 3][row] = b.w;
        }
        __syncthreads();

        #pragma unroll
        for (int k = 0; k < BK; k++) {
            float4 a0 = *(const float4*)&As[k][ty * 8 + 0];
            float4 a1 = *(const float4*)&As[k][ty * 8 + 4];
            float4 b0 = *(const float4*)&Bs[k][tx * 8 + 0];
            float4 b1 = *(const float4*)&Bs[k][tx * 8 + 4];
            float av[8] = {a0.x,a0.y,a0.z,a0.w,a1.x,a1.y,a1.z,a1.w};
            float bv[8] = {b0.x,b0.y,b0.z,b0.w,b1.x,b1.y,b1.z,b1.w};
            #pragma unroll
            for (int i = 0; i < 8; i++)
                #pragma unroll
                for (int j = 0; j < 8; j++)
                    acc[i][j] += av[i] * bv[j];
        }
        __syncthreads();
    }

    #pragma unroll
    for (int i = 0; i < 8; i++) {
        int gr = m0 + ty * 8 + i;
        if (gr < N_NODES) {
            float4 o0 = make_float4(acc[i][0], acc[i][1], acc[i][2], acc[i][3]);
            float4 o1 = make_float4(acc[i][4], acc[i][5], acc[i][6], acc[i][7]);
            *(float4*)&O[gr * OUT_F + tx * 8 + 0] = o0;
            *(float4*)&O[gr * OUT_F + tx * 8 + 4] = o1;
        }
    }
}

// ---------------- CSR build -----------------
__global__ void k_zero()
{
    int i = blockIdx.x * blockDim.x + threadIdx.x;
    if (i < N_NODES) g_cnt[i] = 0;
}

__global__ void k_count(const void* __restrict__ ei)
{
    int e = blockIdx.x * blockDim.x + threadIdx.x;
    if (e < N_EDGES) {
        int r = edge_at(ei, e);
        if ((unsigned)r < N_NODES) atomicAdd(&g_cnt[r], 1);
    }
}

__global__ __launch_bounds__(1024) void k_scan()
{
    __shared__ int sm[1024];
    const int t = threadIdx.x;
    const int chunk = (N_NODES + 1023) / 1024;
    int s0 = t * chunk;
    int s1 = s0 + chunk; if (s1 > N_NODES) s1 = N_NODES;
    if (s0 > N_NODES) s0 = N_NODES;

    int s = 0;
    for (int i = s0; i < s1; i++) s += g_cnt[i];
    sm[t] = s;
    __syncthreads();
    for (int off = 1; off < 1024; off <<= 1) {
        int v = (t >= off) ? sm[t - off] : 0;
        __syncthreads();
        sm[t] += v;
        __syncthreads();
    }
    int run = (t == 0) ? 0 : sm[t - 1];
    for (int i = s0; i < s1; i++) { g_off[i] = run; run += g_cnt[i]; }
    if (t == 1023) g_off[N_NODES] = sm[1023];
}

__global__ void k_cursor()
{
    int i = blockIdx.x * blockDim.x + threadIdx.x;
    if (i < N_NODES) g_cur[i] = g_off[i];
}

__global__ void k_scatter(const void* __restrict__ ei)
{
    int e = blockIdx.x * blockDim.x + threadIdx.x;
    if (e < N_EDGES) {
        int r = edge_at(ei, e);
        int c = edge_at(ei, N_EDGES + e);
        if ((unsigned)r < N_NODES && (unsigned)c < N_NODES) {
            int p = atomicAdd(&g_cur[r], 1);
            g_src[p] = c;
        }
    }
}

// ---------------- per-node online-softmax aggregation -------------
// One warp per destination node. Lane l owns flat dims 4l..4l+3
// (head = l/8). Per-head score reduction = shfl.xor {1,2,4} within octet.
__global__ __launch_bounds__(256) void k_aggregate(
    const float* __restrict__ D, float* __restrict__ out)
{
    int warp = (blockIdx.x * blockDim.x + threadIdx.x) >> 5;
    int lane = threadIdx.x & 31;
    if (warp >= N_NODES) return;
    const int r = warp;

    const int beg = g_off[r];
    const int end = g_off[r + 1];

    const float4 kv = *(const float4*)&g_K[r * OUT_F + lane * 4];
    const float4 Dv = *(const float4*)&D[lane * 4];
    const float scale = 0.1767766952966369f;   // 1/sqrt(32)

    float  m  = -CUDART_INF_F;
    float  sw = 0.f;
    float4 acc = make_float4(0.f, 0.f, 0.f, 0.f);

    for (int e = beg; e < end; ++e) {
        const int c = g_src[e];
        const float4 q = *(const float4*)&g_Q[c * OUT_F + lane * 4];
        const float4 v = *(const float4*)&g_V[c * OUT_F + lane * 4];

        float4 t;
        if (c == r) {
            t.x = kv.x * Dv.x * q.x;
            t.y = kv.y * Dv.y * q.y;
            t.z = kv.z * Dv.z * q.z;
            t.w = kv.w * Dv.w * q.w;
        } else {
            float dx = kv.x - q.x, dy = kv.y - q.y, dz = kv.z - q.z, dw = kv.w - q.w;
            t.x = dx * Dv.x * dx;
            t.y = dy * Dv.y * dy;
            t.z = dz * Dv.z * dz;
            t.w = dw * Dv.w * dw;
        }
        float s = t.x + t.y + t.z + t.w;
        s += __shfl_xor_sync(0xffffffffu, s, 1);
        s += __shfl_xor_sync(0xffffffffu, s, 2);
        s += __shfl_xor_sync(0xffffffffu, s, 4);
        s *= scale;
        s = (s > 0.f) ? s : 0.2f * s;          // leaky_relu(., 0.2)

        float mn   = fmaxf(m, s);
        float corr = __expf(m - mn);
        float w    = __expf(s - mn);
        sw = sw * corr + w;
        acc.x = acc.x * corr + w * v.x;
        acc.y = acc.y * corr + w * v.y;
        acc.z = acc.z * corr + w * v.z;
        acc.w = acc.w * corr + w * v.w;
        m = mn;
    }

    const float inv = 1.f / (sw + 1e-16f);
    float4 o = make_float4(acc.x * inv, acc.y * inv, acc.z * inv, acc.w * inv);
    *(float4*)&out[r * OUT_F + lane * 4] = o;
}

// ---------------- launch -----------------
extern "C" void kernel_launch(void* const* d_in, const int* in_sizes, int n_in,
                              void* d_out, int out_size)
{
    // Bind inputs by unique element counts (robust to metadata ordering).
    const float *x = 0, *Wq = 0, *Wk = 0, *Wv = 0, *D = 0;
    const void  *ei = 0;
    int wcount = 0;
    for (int i = 0; i < n_in; i++) {
        long long sz = in_sizes[i];
        if (sz == (long long)N_NODES * IN_F) {
            x = (const float*)d_in[i];
        } else if (sz == (long long)2 * N_EDGES) {
            ei = d_in[i];
        } else if (sz == (long long)IN_F * OUT_F) {
            if (wcount == 0)      Wq = (const float*)d_in[i];
            else if (wcount == 1) Wk = (const float*)d_in[i];
            else                  Wv = (const float*)d_in[i];
            wcount++;
        } else if (sz == OUT_F) {
            D = (const float*)d_in[i];
        }
    }
    float* out = (float*)d_out;

    // dtype probe for edge_index (int64 vs int32)
    k_detect<<<1, 1>>>(ei);

    // CSR build
    k_zero<<<(N_NODES + 255) / 256, 256>>>();
    k_count<<<(N_EDGES + 255) / 256, 256>>>(ei);
    k_scan<<<1, 1024>>>();
    k_cursor<<<(N_NODES + 255) / 256, 256>>>();
    k_scatter<<<(N_EDGES + 255) / 256, 256>>>(ei);

    // QKV projection
    dim3 gg((N_NODES + 127) / 128, 3);
    qkv_gemm<<<gg, 256>>>(x, Wq, Wk, Wv);

    // fused score + segmented online softmax + aggregation
    k_aggregate<<<(N_NODES * 32 + 255) / 256, 256>>>(D, out);
}

// round 7
// speedup vs baseline: 1.1873x; 1.1873x over previous
#include <cuda_runtime.h>
#include <math_constants.h>

#define N_NODES 100000
#define N_EDGES 1600000
#define IN_F    128
#define OUT_F   128     // HEADS * D_K = 4 * 32
#define NB_SCAN ((N_NODES + 1023) / 1024)   // 98

// ---------------- scratch (no allocations allowed) ----------------
__device__ float g_Q[N_NODES * OUT_F];
__device__ float g_K[N_NODES * OUT_F];
__device__ float g_V[N_NODES * OUT_F];
__device__ int   g_cnt[N_NODES];
__device__ int   g_off[N_NODES + 1];
__device__ int   g_cur[N_NODES];
__device__ int   g_src[N_EDGES];
__device__ int   g_bsum[128];
__device__ int   g_is64;

// ---------------- packed f32x2 helpers (FFMA2: PTX-only on sm_103a) ----
typedef unsigned long long u64;
__device__ __forceinline__ u64 pk2(float lo, float hi)
{
    u64 r; asm("mov.b64 %0,{%1,%2};" : "=l"(r) : "f"(lo), "f"(hi)); return r;
}
__device__ __forceinline__ void upk2(u64 v, float& lo, float& hi)
{
    asm("mov.b64 {%0,%1},%2;" : "=f"(lo), "=f"(hi) : "l"(v));
}
__device__ __forceinline__ void ffma2(u64& d, u64 a, u64 b)
{
    asm("fma.rn.f32x2 %0,%1,%2,%0;" : "+l"(d) : "l"(a), "l"(b));
}

// Edge accessor: ei is either int64[2, E] or int32[2, E]; g_is64 selects.
__device__ __forceinline__ int edge_at(const void* ei, int idx)
{
    if (g_is64) return (int)((const long long*)ei)[idx];
    return ((const int*)ei)[idx];
}

// zero counters + detect edge dtype (thread 0)
__global__ void k_zero(const void* __restrict__ ei)
{
    int i = blockIdx.x * blockDim.x + threadIdx.x;
    if (i < N_NODES) g_cnt[i] = 0;
    if (i == 0) {
        const long long* p = (const long long*)ei;
        bool ok = true;
        #pragma unroll
        for (int k = 0; k < 8; k++) {
            long long v = p[k];
            if (v < 0 || v >= N_NODES) ok = false;
        }
        g_is64 = ok ? 1 : 0;
    }
}

// ---------------- QKV projection: out = x @ W^T -------------------
// SGEMM, BM=BN=128, BK=16, 256 threads, 8x8 register tile, FFMA2 inner loop.
__global__ __launch_bounds__(256) void qkv_gemm(
    const float* __restrict__ x,
    const float* __restrict__ Wq,
    const float* __restrict__ Wk,
    const float* __restrict__ Wv)
{
    const int BM = 128, BK = 16;
    __shared__ float As[BK][132];
    __shared__ float Bs[BK][132];

    const float* W;
    float* O;
    if (blockIdx.y == 0)      { W = Wq; O = g_Q; }
    else if (blockIdx.y == 1) { W = Wk; O = g_K; }
    else                      { W = Wv; O = g_V; }

    const int m0  = blockIdx.x * BM;
    const int tid = threadIdx.x;

    const int l_r = tid >> 2;          // 0..63 (rows l_r and l_r+64)
    const int l_c = (tid & 3) << 2;    // 0,4,8,12

    const int ty = tid >> 4;           // 0..15
    const int tx = tid & 15;           // 0..15

    u64 acc2[8][4];
    #pragma unroll
    for (int i = 0; i < 8; i++)
        #pragma unroll
        for (int j = 0; j < 4; j++) acc2[i][j] = 0ull;

    for (int kk = 0; kk < IN_F; kk += BK) {
        #pragma unroll
        for (int h = 0; h < 2; h++) {
            int row = l_r + h * 64;
            int gr  = m0 + row;
            float4 a = make_float4(0.f, 0.f, 0.f, 0.f);
            if (gr < N_NODES)
                a = *(const float4*)&x[gr * IN_F + kk + l_c];
            As[l_c + 0][row] = a.x;
            As[l_c + 1][row] = a.y;
            As[l_c + 2][row] = a.z;
            As[l_c + 3][row] = a.w;
        }
        #pragma unroll
        for (int h = 0; h < 2; h++) {
            int row = l_r + h * 64;
            float4 b = *(const float4*)&W[row * IN_F + kk + l_c];
            Bs[l_c + 0][row] = b.x;
            Bs[l_c + 1][row] = b.y;
            Bs[l_c + 2][row] = b.z;
            Bs[l_c + 3][row] = b.w;
        }
        __syncthreads();

        #pragma unroll
        for (int k = 0; k < BK; k++) {
            float4 a0 = *(const float4*)&As[k][ty * 8 + 0];
            float4 a1 = *(const float4*)&As[k][ty * 8 + 4];
            float4 b0 = *(const float4*)&Bs[k][tx * 8 + 0];
            float4 b1 = *(const float4*)&Bs[k][tx * 8 + 4];
            u64 bv[4] = { pk2(b0.x, b0.y), pk2(b0.z, b0.w),
                          pk2(b1.x, b1.y), pk2(b1.z, b1.w) };
            float av[8] = {a0.x,a0.y,a0.z,a0.w,a1.x,a1.y,a1.z,a1.w};
            #pragma unroll
            for (int i = 0; i < 8; i++) {
                u64 a2 = pk2(av[i], av[i]);
                #pragma unroll
                for (int j = 0; j < 4; j++)
                    ffma2(acc2[i][j], a2, bv[j]);
            }
        }
        __syncthreads();
    }

    #pragma unroll
    for (int i = 0; i < 8; i++) {
        int gr = m0 + ty * 8 + i;
        if (gr < N_NODES) {
            float o[8];
            #pragma unroll
            for (int j = 0; j < 4; j++) upk2(acc2[i][j], o[2*j], o[2*j+1]);
            *(float4*)&O[gr * OUT_F + tx * 8 + 0] = make_float4(o[0], o[1], o[2], o[3]);
            *(float4*)&O[gr * OUT_F + tx * 8 + 4] = make_float4(o[4], o[5], o[6], o[7]);
        }
    }
}

// ---------------- CSR build -----------------
__global__ void k_count(const void* __restrict__ ei)
{
    int e = blockIdx.x * blockDim.x + threadIdx.x;
    if (e < N_EDGES) {
        int r = edge_at(ei, e);
        if ((unsigned)r < N_NODES) atomicAdd(&g_cnt[r], 1);
    }
}

// two-level scan: block scans (98 blocks x 1024), scan of partials, add-back
__global__ __launch_bounds__(1024) void k_scan1()
{
    __shared__ int wsum[32];
    int i = blockIdx.x * 1024 + threadIdx.x;
    int v = (i < N_NODES) ? g_cnt[i] : 0;
    int lane = threadIdx.x & 31, w = threadIdx.x >> 5;

    int s = v;
    #pragma unroll
    for (int o = 1; o < 32; o <<= 1) {
        int t = __shfl_up_sync(0xffffffffu, s, o);
        if (lane >= o) s += t;
    }
    if (lane == 31) wsum[w] = s;
    __syncthreads();
    if (w == 0) {
        int t = wsum[lane];
        #pragma unroll
        for (int o = 1; o < 32; o <<= 1) {
            int u = __shfl_up_sync(0xffffffffu, t, o);
            if (lane >= o) t += u;
        }
        wsum[lane] = t;
    }
    __syncthreads();
    int excl = s - v + (w ? wsum[w - 1] : 0);
    if (i < N_NODES) g_off[i] = excl;
    if (threadIdx.x == 1023) g_bsum[blockIdx.x] = wsum[31];
}

__global__ void k_scan2()
{
    __shared__ int sm[128];
    int t = threadIdx.x;
    int v = (t < NB_SCAN) ? g_bsum[t] : 0;
    sm[t] = v;
    __syncthreads();
    for (int o = 1; o < 128; o <<= 1) {
        int u = (t >= o) ? sm[t - o] : 0;
        __syncthreads();
        sm[t] += u;
        __syncthreads();
    }
    if (t < NB_SCAN) g_bsum[t] = sm[t] - v;   // exclusive
    if (t == 127) g_off[N_NODES] = sm[127];
}

__global__ __launch_bounds__(1024) void k_scan3()
{
    int i = blockIdx.x * 1024 + threadIdx.x;
    if (i < N_NODES) {
        int o = g_off[i] + g_bsum[blockIdx.x];
        g_off[i] = o;
        g_cur[i] = o;
    }
}

__global__ void k_scatter(const void* __restrict__ ei)
{
    int e = blockIdx.x * blockDim.x + threadIdx.x;
    if (e < N_EDGES) {
        int r = edge_at(ei, e);
        int c = edge_at(ei, N_EDGES + e);
        if ((unsigned)r < N_NODES && (unsigned)c < N_NODES) {
            int p = atomicAdd(&g_cur[r], 1);
            g_src[p] = c;
        }
    }
}

// ---------------- per-node online-softmax aggregation -------------
// One warp per destination node. Lane l owns flat dims 4l..4l+3
// (head = l/8). Per-head score reduction = shfl.xor {1,2,4} within octet.
__global__ __launch_bounds__(256) void k_aggregate(
    const float* __restrict__ D, float* __restrict__ out)
{
    int warp = (blockIdx.x * blockDim.x + threadIdx.x) >> 5;
    int lane = threadIdx.x & 31;
    if (warp >= N_NODES) return;
    const int r = warp;

    const int beg = g_off[r];
    const int end = g_off[r + 1];

    const float4 kv = *(const float4*)&g_K[r * OUT_F + lane * 4];
    const float4 Dv = *(const float4*)&D[lane * 4];
    const float scale = 0.1767766952966369f;   // 1/sqrt(32)

    float  m  = -CUDART_INF_F;
    float  sw = 0.f;
    float4 acc = make_float4(0.f, 0.f, 0.f, 0.f);

    for (int e = beg; e < end; ++e) {
        const int c = g_src[e];
        const float4 q = *(const float4*)&g_Q[c * OUT_F + lane * 4];
        const float4 v = *(const float4*)&g_V[c * OUT_F + lane * 4];

        float4 t;
        if (c == r) {
            t.x = kv.x * Dv.x * q.x;
            t.y = kv.y * Dv.y * q.y;
            t.z = kv.z * Dv.z * q.z;
            t.w = kv.w * Dv.w * q.w;
        } else {
            float dx = kv.x - q.x, dy = kv.y - q.y, dz = kv.z - q.z, dw = kv.w - q.w;
            t.x = dx * Dv.x * dx;
            t.y = dy * Dv.y * dy;
            t.z = dz * Dv.z * dz;
            t.w = dw * Dv.w * dw;
        }
        float s = t.x + t.y + t.z + t.w;
        s += __shfl_xor_sync(0xffffffffu, s, 1);
        s += __shfl_xor_sync(0xffffffffu, s, 2);
        s += __shfl_xor_sync(0xffffffffu, s, 4);
        s *= scale;
        s = (s > 0.f) ? s : 0.2f * s;          // leaky_relu(., 0.2)

        float mn   = fmaxf(m, s);
        float corr = __expf(m - mn);
        float w    = __expf(s - mn);
        sw = sw * corr + w;
        acc.x = acc.x * corr + w * v.x;
        acc.y = acc.y * corr + w * v.y;
        acc.z = acc.z * corr + w * v.z;
        acc.w = acc.w * corr + w * v.w;
        m = mn;
    }

    const float inv = 1.f / (sw + 1e-16f);
    float4 o = make_float4(acc.x * inv, acc.y * inv, acc.z * inv, acc.w * inv);
    *(float4*)&out[r * OUT_F + lane * 4] = o;
}

// ---------------- launch -----------------
extern "C" void kernel_launch(void* const* d_in, const int* in_sizes, int n_in,
                              void* d_out, int out_size)
{
    // Bind inputs by unique element counts (robust to metadata ordering).
    const float *x = 0, *Wq = 0, *Wk = 0, *Wv = 0, *D = 0;
    const void  *ei = 0;
    int wcount = 0;
    for (int i = 0; i < n_in; i++) {
        long long sz = in_sizes[i];
        if (sz == (long long)N_NODES * IN_F) {
            x = (const float*)d_in[i];
        } else if (sz == (long long)2 * N_EDGES) {
            ei = d_in[i];
        } else if (sz == (long long)IN_F * OUT_F) {
            if (wcount == 0)      Wq = (const float*)d_in[i];
            else if (wcount == 1) Wk = (const float*)d_in[i];
            else                  Wv = (const float*)d_in[i];
            wcount++;
        } else if (sz == OUT_F) {
            D = (const float*)d_in[i];
        }
    }
    float* out = (float*)d_out;

    // CSR build (zero fuses the dtype probe)
    k_zero<<<(N_NODES + 255) / 256, 256>>>(ei);
    k_count<<<(N_EDGES + 255) / 256, 256>>>(ei);
    k_scan1<<<NB_SCAN, 1024>>>();
    k_scan2<<<1, 128>>>();
    k_scan3<<<NB_SCAN, 1024>>>();
    k_scatter<<<(N_EDGES + 255) / 256, 256>>>(ei);

    // QKV projection
    dim3 gg((N_NODES + 127) / 128, 3);
    qkv_gemm<<<gg, 256>>>(x, Wq, Wk, Wv);

    // fused score + segmented online softmax + aggregation
    k_aggregate<<<(N_NODES * 32 + 255) / 256, 256>>>(D, out);
}

// round 9
// speedup vs baseline: 1.3451x; 1.1329x over previous
#include <cuda_runtime.h>
#include <cuda_bf16.h>
#include <math_constants.h>
#include <cstdint>

#define N_NODES 100000
#define N_EDGES 1600000
#define IN_F    128
#define OUT_F   128     // HEADS * D_K = 4 * 32
#define NB_SCAN ((N_NODES + 1023) / 1024)   // 98
#define NTILES  ((N_NODES + 127) / 128)     // 782

// ---------------- scratch (no allocations allowed) ----------------
__device__ float g_Q[N_NODES * OUT_F];
__device__ float g_K[N_NODES * OUT_F];
__device__ float g_V[N_NODES * OUT_F];
__device__ int   g_cnt[N_NODES];
__device__ int   g_off[N_NODES + 1];
__device__ int   g_cur[N_NODES];
__device__ int   g_src[N_EDGES];
__device__ int   g_bsum[128];
__device__ int   g_is64;
// bf16 hi/lo images, row-major [row][128]
__device__ __nv_bfloat16 g_Xhi[(size_t)NTILES * 128 * IN_F];
__device__ __nv_bfloat16 g_Xlo[(size_t)NTILES * 128 * IN_F];
__device__ __nv_bfloat16 g_Wb[3][2][OUT_F * IN_F];

// ---------------- mma.sync helpers (base sm_103 legal) ----------------
__device__ __forceinline__ uint32_t smem_u32(const void* p)
{
    uint32_t a;
    asm("{ .reg .u64 t; cvta.to.shared.u64 t, %1; cvt.u32.u64 %0, t; }"
        : "=r"(a) : "l"(p));
    return a;
}
__device__ __forceinline__ void ldsm4(uint32_t& r0, uint32_t& r1, uint32_t& r2,
                                      uint32_t& r3, uint32_t addr)
{
    asm volatile("ldmatrix.sync.aligned.m8n8.x4.shared.b16 {%0,%1,%2,%3}, [%4];"
                 : "=r"(r0), "=r"(r1), "=r"(r2), "=r"(r3) : "r"(addr));
}
__device__ __forceinline__ void mma16816(float* c,
                                         uint32_t a0, uint32_t a1, uint32_t a2, uint32_t a3,
                                         uint32_t b0, uint32_t b1)
{
    asm volatile("mma.sync.aligned.m16n8k16.row.col.f32.bf16.bf16.f32 "
                 "{%0,%1,%2,%3}, {%4,%5,%6,%7}, {%8,%9}, {%0,%1,%2,%3};"
                 : "+f"(c[0]), "+f"(c[1]), "+f"(c[2]), "+f"(c[3])
                 : "r"(a0), "r"(a1), "r"(a2), "r"(a3), "r"(b0), "r"(b1));
}
// swizzled smem addr: 128B rows of 8x16B chunks, chunk XOR (row&7)
__device__ __forceinline__ uint32_t sw_addr(uint32_t base, int row, int kchunk)
{
    return base + (uint32_t)(row << 7) + (uint32_t)(((kchunk ^ (row & 7)) & 7) << 4);
}

// Edge accessor: ei is either int64[2, E] or int32[2, E]; g_is64 selects.
__device__ __forceinline__ int edge_at(const void* ei, int idx)
{
    if (g_is64) return (int)((const long long*)ei)[idx];
    return ((const int*)ei)[idx];
}

// zero counters + detect edge dtype (thread 0)
__global__ void k_zero(const void* __restrict__ ei)
{
    int i = blockIdx.x * blockDim.x + threadIdx.x;
    if (i < N_NODES) g_cnt[i] = 0;
    if (i == 0) {
        const long long* p = (const long long*)ei;
        bool ok = true;
        #pragma unroll
        for (int k = 0; k < 8; k++) {
            long long v = p[k];
            if (v < 0 || v >= N_NODES) ok = false;
        }
        g_is64 = ok ? 1 : 0;
    }
}

// ---------------- bf16 hi/lo pre-conversion (row-major) ----------------
__global__ void k_wconv(const float* __restrict__ Wq,
                        const float* __restrict__ Wk,
                        const float* __restrict__ Wv)
{
    int mat = blockIdx.x;
    const float* W = (mat == 0) ? Wq : (mat == 1) ? Wk : Wv;
    int row = threadIdx.x;            // output-feature 0..127
    #pragma unroll 4
    for (int c8 = 0; c8 < 16; c8++) {
        union { __nv_bfloat16 b[8]; uint4 v; } H, L;
        #pragma unroll
        for (int j = 0; j < 8; j++) {
            float f = W[row * IN_F + c8 * 8 + j];
            __nv_bfloat16 h = __float2bfloat16(f);
            H.b[j] = h;
            L.b[j] = __float2bfloat16(f - __bfloat162float(h));
        }
        *(uint4*)&g_Wb[mat][0][row * IN_F + c8 * 8] = H.v;
        *(uint4*)&g_Wb[mat][1][row * IN_F + c8 * 8] = L.v;
    }
}

__global__ __launch_bounds__(128) void k_xconv(const float* __restrict__ x)
{
    int gr = blockIdx.x * 128 + threadIdx.x;
    size_t base = (size_t)gr * IN_F;
    #pragma unroll 4
    for (int c8 = 0; c8 < 16; c8++) {
        union { __nv_bfloat16 b[8]; uint4 v; } H, L;
        if (gr < N_NODES) {
            const float4 f0 = *(const float4*)&x[base + c8 * 8 + 0];
            const float4 f1 = *(const float4*)&x[base + c8 * 8 + 4];
            float fs[8] = {f0.x,f0.y,f0.z,f0.w,f1.x,f1.y,f1.z,f1.w};
            #pragma unroll
            for (int j = 0; j < 8; j++) {
                __nv_bfloat16 h = __float2bfloat16(fs[j]);
                H.b[j] = h;
                L.b[j] = __float2bfloat16(fs[j] - __bfloat162float(h));
            }
        } else {
            H.v = make_uint4(0,0,0,0);
            L.v = make_uint4(0,0,0,0);
        }
        *(uint4*)&g_Xhi[base + c8 * 8] = H.v;
        *(uint4*)&g_Xlo[base + c8 * 8] = L.v;
    }
}

// ---------------- HMMA QKV GEMM ----------------
// grid (NTILES, 3), 256 threads (8 warps, 32x64 warp tiles).
// O = X @ W^T, 3-term bf16 split (hi*hi + hi*lo + lo*hi), fp32 accum.
// SMEM 64KB: A hi/lo + B hi/lo K-chunks of 64, swizzled for ldmatrix.
__global__ __launch_bounds__(256, 2) void qkv_hmma()
{
    extern __shared__ __align__(1024) unsigned char dsm[];
    const uint32_t sbase = smem_u32(dsm);
    const uint32_t Ah = sbase, Al = sbase + 16384, Bh = sbase + 32768, Bl = sbase + 49152;

    const int tile = blockIdx.x, mat = blockIdx.y;
    const int tid = threadIdx.x, wid = tid >> 5, lane = tid & 31;
    const int wm = (wid & 3) * 32;        // warp M offset
    const int wn = (wid >> 2) * 64;       // warp N offset

    const __nv_bfloat16* xh = g_Xhi + (size_t)tile * 128 * IN_F;
    const __nv_bfloat16* xl = g_Xlo + (size_t)tile * 128 * IN_F;
    const __nv_bfloat16* wh = g_Wb[mat][0];
    const __nv_bfloat16* wl = g_Wb[mat][1];

    float acc[2][8][4];
    #pragma unroll
    for (int mi = 0; mi < 2; mi++)
        #pragma unroll
        for (int nf = 0; nf < 8; nf++)
            #pragma unroll
            for (int j = 0; j < 4; j++) acc[mi][nf][j] = 0.f;

    for (int kc = 0; kc < IN_F; kc += 64) {
        if (kc) __syncthreads();
        // load 4 tiles of [128 rows x 64 bf16] into swizzled smem
        #pragma unroll
        for (int i = tid; i < 1024; i += 256) {
            int row = i >> 3, ch = i & 7;
            uint32_t dst_off = (uint32_t)(row << 7) + (uint32_t)(((ch ^ (row & 7)) & 7) << 4);
            size_t src = (size_t)row * IN_F + kc + ch * 8;
            *(uint4*)(dsm + (Ah - sbase) + dst_off) = *(const uint4*)&xh[src];
            *(uint4*)(dsm + (Al - sbase) + dst_off) = *(const uint4*)&xl[src];
            *(uint4*)(dsm + (Bh - sbase) + dst_off) = *(const uint4*)&wh[src];
            *(uint4*)(dsm + (Bl - sbase) + dst_off) = *(const uint4*)&wl[src];
        }
        __syncthreads();

        #pragma unroll
        for (int term = 0; term < 3; term++) {
            const uint32_t Ab = (term == 2) ? Al : Ah;
            const uint32_t Bb = (term == 1) ? Bl : Bh;
            #pragma unroll
            for (int kl = 0; kl < 64; kl += 16) {
                const int kch = (kl >> 3) + (lane >> 4);
                uint32_t a[2][4];
                #pragma unroll
                for (int mi = 0; mi < 2; mi++) {
                    int arow = wm + mi * 16 + (lane & 15);
                    ldsm4(a[mi][0], a[mi][1], a[mi][2], a[mi][3], sw_addr(Ab, arow, kch));
                }
                #pragma unroll
                for (int q = 0; q < 4; q++) {
                    int brow = wn + q * 16 + (lane & 15);
                    uint32_t r0, r1, r2, r3;
                    ldsm4(r0, r1, r2, r3, sw_addr(Bb, brow, kch));
                    #pragma unroll
                    for (int mi = 0; mi < 2; mi++) {
                        mma16816(acc[mi][q * 2 + 0], a[mi][0], a[mi][1], a[mi][2], a[mi][3], r0, r2);
                        mma16816(acc[mi][q * 2 + 1], a[mi][0], a[mi][1], a[mi][2], a[mi][3], r1, r3);
                    }
                }
            }
        }
    }

    // epilogue: c0,c1 -> (row t/4, col 2(t%4)); c2,c3 -> row+8
    float* O = (mat == 0) ? g_Q : (mat == 1) ? g_K : g_V;
    const int tq = lane >> 2, tr = lane & 3;
    #pragma unroll
    for (int mi = 0; mi < 2; mi++) {
        int r0 = tile * 128 + wm + mi * 16 + tq;
        #pragma unroll
        for (int nf = 0; nf < 8; nf++) {
            int col = wn + nf * 8 + tr * 2;
            if (r0 < N_NODES)
                *(float2*)&O[(size_t)r0 * OUT_F + col] = make_float2(acc[mi][nf][0], acc[mi][nf][1]);
            if (r0 + 8 < N_NODES)
                *(float2*)&O[(size_t)(r0 + 8) * OUT_F + col] = make_float2(acc[mi][nf][2], acc[mi][nf][3]);
        }
    }
}

// ---------------- CSR build -----------------
__global__ void k_count(const void* __restrict__ ei)
{
    int e = blockIdx.x * blockDim.x + threadIdx.x;
    if (e < N_EDGES) {
        int r = edge_at(ei, e);
        if ((unsigned)r < N_NODES) atomicAdd(&g_cnt[r], 1);
    }
}

__global__ __launch_bounds__(1024) void k_scan1()
{
    __shared__ int wsum[32];
    int i = blockIdx.x * 1024 + threadIdx.x;
    int v = (i < N_NODES) ? g_cnt[i] : 0;
    int lane = threadIdx.x & 31, w = threadIdx.x >> 5;

    int s = v;
    #pragma unroll
    for (int o = 1; o < 32; o <<= 1) {
        int t = __shfl_up_sync(0xffffffffu, s, o);
        if (lane >= o) s += t;
    }
    if (lane == 31) wsum[w] = s;
    __syncthreads();
    if (w == 0) {
        int t = wsum[lane];
        #pragma unroll
        for (int o = 1; o < 32; o <<= 1) {
            int u = __shfl_up_sync(0xffffffffu, t, o);
            if (lane >= o) t += u;
        }
        wsum[lane] = t;
    }
    __syncthreads();
    int excl = s - v + (w ? wsum[w - 1] : 0);
    if (i < N_NODES) g_off[i] = excl;
    if (threadIdx.x == 1023) g_bsum[blockIdx.x] = wsum[31];
}

__global__ void k_scan2()
{
    __shared__ int sm[128];
    int t = threadIdx.x;
    int v = (t < NB_SCAN) ? g_bsum[t] : 0;
    sm[t] = v;
    __syncthreads();
    for (int o = 1; o < 128; o <<= 1) {
        int u = (t >= o) ? sm[t - o] : 0;
        __syncthreads();
        sm[t] += u;
        __syncthreads();
    }
    if (t < NB_SCAN) g_bsum[t] = sm[t] - v;   // exclusive
    if (t == 127) g_off[N_NODES] = sm[127];
}

__global__ __launch_bounds__(1024) void k_scan3()
{
    int i = blockIdx.x * 1024 + threadIdx.x;
    if (i < N_NODES) {
        int o = g_off[i] + g_bsum[blockIdx.x];
        g_off[i] = o;
        g_cur[i] = o;
    }
}

__global__ void k_scatter(const void* __restrict__ ei)
{
    int e = blockIdx.x * blockDim.x + threadIdx.x;
    if (e < N_EDGES) {
        int r = edge_at(ei, e);
        int c = edge_at(ei, N_EDGES + e);
        if ((unsigned)r < N_NODES && (unsigned)c < N_NODES) {
            int p = atomicAdd(&g_cur[r], 1);
            g_src[p] = c;
        }
    }
}

// ---------------- per-node online-softmax aggregation -------------
__global__ __launch_bounds__(256) void k_aggregate(
    const float* __restrict__ D, float* __restrict__ out)
{
    int warp = (blockIdx.x * blockDim.x + threadIdx.x) >> 5;
    int lane = threadIdx.x & 31;
    if (warp >= N_NODES) return;
    const int r = warp;

    const int beg = g_off[r];
    const int end = g_off[r + 1];

    const float4 kv = *(const float4*)&g_K[(size_t)r * OUT_F + lane * 4];
    const float4 Dv = *(const float4*)&D[lane * 4];
    const float scale = 0.1767766952966369f;   // 1/sqrt(32)

    float  m  = -CUDART_INF_F;
    float  sw = 0.f;
    float4 acc = make_float4(0.f, 0.f, 0.f, 0.f);

    for (int e = beg; e < end; ++e) {
        const int c = g_src[e];
        const float4 q = *(const float4*)&g_Q[(size_t)c * OUT_F + lane * 4];
        const float4 v = *(const float4*)&g_V[(size_t)c * OUT_F + lane * 4];

        float4 t;
        if (c == r) {
            t.x = kv.x * Dv.x * q.x;
            t.y = kv.y * Dv.y * q.y;
            t.z = kv.z * Dv.z * q.z;
            t.w = kv.w * Dv.w * q.w;
        } else {
            float dx = kv.x - q.x, dy = kv.y - q.y, dz = kv.z - q.z, dw = kv.w - q.w;
            t.x = dx * Dv.x * dx;
            t.y = dy * Dv.y * dy;
            t.z = dz * Dv.z * dz;
            t.w = dw * Dv.w * dw;
        }
        float s = t.x + t.y + t.z + t.w;
        s += __shfl_xor_sync(0xffffffffu, s, 1);
        s += __shfl_xor_sync(0xffffffffu, s, 2);
        s += __shfl_xor_sync(0xffffffffu, s, 4);
        s *= scale;
        s = (s > 0.f) ? s : 0.2f * s;          // leaky_relu(., 0.2)

        float mn   = fmaxf(m, s);
        float corr = __expf(m - mn);
        float w    = __expf(s - mn);
        sw = sw * corr + w;
        acc.x = acc.x * corr + w * v.x;
        acc.y = acc.y * corr + w * v.y;
        acc.z = acc.z * corr + w * v.z;
        acc.w = acc.w * corr + w * v.w;
        m = mn;
    }

    const float inv = 1.f / (sw + 1e-16f);
    float4 o = make_float4(acc.x * inv, acc.y * inv, acc.z * inv, acc.w * inv);
    *(float4*)&out[(size_t)r * OUT_F + lane * 4] = o;
}

// ---------------- launch -----------------
extern "C" void kernel_launch(void* const* d_in, const int* in_sizes, int n_in,
                              void* d_out, int out_size)
{
    const float *x = 0, *Wq = 0, *Wk = 0, *Wv = 0, *D = 0;
    const void  *ei = 0;
    int wcount = 0;
    for (int i = 0; i < n_in; i++) {
        long long sz = in_sizes[i];
        if (sz == (long long)N_NODES * IN_F) {
            x = (const float*)d_in[i];
        } else if (sz == (long long)2 * N_EDGES) {
            ei = d_in[i];
        } else if (sz == (long long)IN_F * OUT_F) {
            if (wcount == 0)      Wq = (const float*)d_in[i];
            else if (wcount == 1) Wk = (const float*)d_in[i];
            else                  Wv = (const float*)d_in[i];
            wcount++;
        } else if (sz == OUT_F) {
            D = (const float*)d_in[i];
        }
    }
    float* out = (float*)d_out;

    const int SMEM_DYN = 65536;
    cudaFuncSetAttribute(qkv_hmma, cudaFuncAttributeMaxDynamicSharedMemorySize, SMEM_DYN);

    // launches ordered so qkv_hmma is launch index 5 (ncu -s 5 -c 1 captures it)
    k_wconv<<<3, 128>>>(Wq, Wk, Wv);                         // 0
    k_xconv<<<NTILES, 128>>>(x);                             // 1
    k_zero<<<(N_NODES + 255) / 256, 256>>>(ei);              // 2
    k_count<<<(N_EDGES + 255) / 256, 256>>>(ei);             // 3
    k_scan1<<<NB_SCAN, 1024>>>();                            // 4
    dim3 gg(NTILES, 3);
    qkv_hmma<<<gg, 256, SMEM_DYN>>>();                       // 5  <- profiled
    k_scan2<<<1, 128>>>();                                   // 6
    k_scan3<<<NB_SCAN, 1024>>>();                            // 7
    k_scatter<<<(N_EDGES + 255) / 256, 256>>>(ei);           // 8
    k_aggregate<<<(N_NODES * 32 + 255) / 256, 256>>>(D, out);// 9
}

// round 10
// speedup vs baseline: 1.5930x; 1.1844x over previous
#include <cuda_runtime.h>
#include <cuda_bf16.h>
#include <math_constants.h>
#include <cstdint>

#define N_NODES 100000
#define N_EDGES 1600000
#define IN_F    128
#define OUT_F   128     // HEADS * D_K = 4 * 32
#define NB_SCAN ((N_NODES + 1023) / 1024)   // 98
#define NTILES  ((N_NODES + 127) / 128)     // 782

// ---------------- scratch (no allocations allowed) ----------------
__device__ float g_Q[N_NODES * OUT_F];
__device__ float g_K[N_NODES * OUT_F];
__device__ float g_V[N_NODES * OUT_F];
__device__ int   g_cnt[N_NODES];
__device__ int   g_off[N_NODES + 1];
__device__ int   g_cur[N_NODES];
__device__ int   g_src[N_EDGES];
__device__ int   g_bsum[128];
__device__ int   g_is64;
// bf16 hi/lo weight images, row-major [row][128]
__device__ __nv_bfloat16 g_Wb[3][2][OUT_F * IN_F];

// ---------------- mma.sync helpers (base sm_103 legal) ----------------
__device__ __forceinline__ uint32_t smem_u32(const void* p)
{
    uint32_t a;
    asm("{ .reg .u64 t; cvta.to.shared.u64 t, %1; cvt.u32.u64 %0, t; }"
        : "=r"(a) : "l"(p));
    return a;
}
__device__ __forceinline__ void ldsm4(uint32_t& r0, uint32_t& r1, uint32_t& r2,
                                      uint32_t& r3, uint32_t addr)
{
    asm volatile("ldmatrix.sync.aligned.m8n8.x4.shared.b16 {%0,%1,%2,%3}, [%4];"
                 : "=r"(r0), "=r"(r1), "=r"(r2), "=r"(r3) : "r"(addr));
}
__device__ __forceinline__ void mma16816(float* c,
                                         uint32_t a0, uint32_t a1, uint32_t a2, uint32_t a3,
                                         uint32_t b0, uint32_t b1)
{
    asm volatile("mma.sync.aligned.m16n8k16.row.col.f32.bf16.bf16.f32 "
                 "{%0,%1,%2,%3}, {%4,%5,%6,%7}, {%8,%9}, {%0,%1,%2,%3};"
                 : "+f"(c[0]), "+f"(c[1]), "+f"(c[2]), "+f"(c[3])
                 : "r"(a0), "r"(a1), "r"(a2), "r"(a3), "r"(b0), "r"(b1));
}
// swizzled smem addr: 128B rows of 8x16B chunks, chunk XOR (row&7)
__device__ __forceinline__ uint32_t sw_addr(uint32_t base, int row, int kchunk)
{
    return base + (uint32_t)(row << 7) + (uint32_t)(((kchunk ^ (row & 7)) & 7) << 4);
}

// Edge accessor: ei is either int64[2, E] or int32[2, E]; g_is64 selects.
__device__ __forceinline__ int edge_at(const void* ei, int idx)
{
    if (g_is64) return (int)((const long long*)ei)[idx];
    return ((const int*)ei)[idx];
}

// zero counters + detect edge dtype (thread 0)
__global__ void k_zero(const void* __restrict__ ei)
{
    int i = blockIdx.x * blockDim.x + threadIdx.x;
    if (i < N_NODES) g_cnt[i] = 0;
    if (i == 0) {
        const long long* p = (const long long*)ei;
        bool ok = true;
        #pragma unroll
        for (int k = 0; k < 8; k++) {
            long long v = p[k];
            if (v < 0 || v >= N_NODES) ok = false;
        }
        g_is64 = ok ? 1 : 0;
    }
}

// ---------------- bf16 hi/lo weight pre-conversion ----------------
__global__ void k_wconv(const float* __restrict__ Wq,
                        const float* __restrict__ Wk,
                        const float* __restrict__ Wv)
{
    int mat = blockIdx.x;
    const float* W = (mat == 0) ? Wq : (mat == 1) ? Wk : Wv;
    int row = threadIdx.x;            // output-feature 0..127
    #pragma unroll 4
    for (int c8 = 0; c8 < 16; c8++) {
        union { __nv_bfloat16 b[8]; uint4 v; } H, L;
        #pragma unroll
        for (int j = 0; j < 8; j++) {
            float f = W[row * IN_F + c8 * 8 + j];
            __nv_bfloat16 h = __float2bfloat16(f);
            H.b[j] = h;
            L.b[j] = __float2bfloat16(f - __bfloat162float(h));
        }
        *(uint4*)&g_Wb[mat][0][row * IN_F + c8 * 8] = H.v;
        *(uint4*)&g_Wb[mat][1][row * IN_F + c8 * 8] = L.v;
    }
}

// ---------------- HMMA QKV GEMM (x converted in-kernel) ----------------
// grid (NTILES, 3), 256 threads (8 warps, 32x64 warp tiles).
// O = X @ W^T, 3-term bf16 split (hi*hi + hi*lo + lo*hi), fp32 accum.
// SMEM 64KB: A hi/lo + B hi/lo K-chunks of 64, swizzled for ldmatrix.
__global__ __launch_bounds__(256, 2) void qkv_hmma(const float* __restrict__ xp)
{
    extern __shared__ __align__(1024) unsigned char dsm[];
    const uint32_t sbase = smem_u32(dsm);
    const uint32_t Ah = sbase, Al = sbase + 16384, Bh = sbase + 32768, Bl = sbase + 49152;

    const int tile = blockIdx.x, mat = blockIdx.y;
    const int tid = threadIdx.x, wid = tid >> 5, lane = tid & 31;
    const int wm = (wid & 3) * 32;        // warp M offset
    const int wn = (wid >> 2) * 64;       // warp N offset

    const __nv_bfloat16* wh = g_Wb[mat][0];
    const __nv_bfloat16* wl = g_Wb[mat][1];

    float acc[2][8][4];
    #pragma unroll
    for (int mi = 0; mi < 2; mi++)
        #pragma unroll
        for (int nf = 0; nf < 8; nf++)
            #pragma unroll
            for (int j = 0; j < 4; j++) acc[mi][nf][j] = 0.f;

    for (int kc = 0; kc < IN_F; kc += 64) {
        if (kc) __syncthreads();
        // A: read x fp32, split into bf16 hi/lo, store swizzled
        // B: copy pre-baked bf16 weight rows, store swizzled
        #pragma unroll
        for (int i = tid; i < 1024; i += 256) {
            int row = i >> 3, ch = i & 7;
            uint32_t dst = (uint32_t)(row << 7) + (uint32_t)(((ch ^ (row & 7)) & 7) << 4);
            int gr = tile * 128 + row;
            union { __nv_bfloat16 b[8]; uint4 v; } H, L;
            if (gr < N_NODES) {
                const float4 f0 = *(const float4*)&xp[(size_t)gr * IN_F + kc + ch * 8 + 0];
                const float4 f1 = *(const float4*)&xp[(size_t)gr * IN_F + kc + ch * 8 + 4];
                float fs[8] = {f0.x,f0.y,f0.z,f0.w,f1.x,f1.y,f1.z,f1.w};
                #pragma unroll
                for (int j = 0; j < 8; j++) {
                    __nv_bfloat16 h = __float2bfloat16(fs[j]);
                    H.b[j] = h;
                    L.b[j] = __float2bfloat16(fs[j] - __bfloat162float(h));
                }
            } else {
                H.v = make_uint4(0,0,0,0);
                L.v = make_uint4(0,0,0,0);
            }
            *(uint4*)(dsm + (Ah - sbase) + dst) = H.v;
            *(uint4*)(dsm + (Al - sbase) + dst) = L.v;
            size_t wsrc = (size_t)row * IN_F + kc + ch * 8;
            *(uint4*)(dsm + (Bh - sbase) + dst) = *(const uint4*)&wh[wsrc];
            *(uint4*)(dsm + (Bl - sbase) + dst) = *(const uint4*)&wl[wsrc];
        }
        __syncthreads();

        #pragma unroll
        for (int term = 0; term < 3; term++) {
            const uint32_t Ab = (term == 2) ? Al : Ah;
            const uint32_t Bb = (term == 1) ? Bl : Bh;
            #pragma unroll
            for (int kl = 0; kl < 64; kl += 16) {
                const int kch = (kl >> 3) + (lane >> 4);
                uint32_t a[2][4];
                #pragma unroll
                for (int mi = 0; mi < 2; mi++) {
                    int arow = wm + mi * 16 + (lane & 15);
                    ldsm4(a[mi][0], a[mi][1], a[mi][2], a[mi][3], sw_addr(Ab, arow, kch));
                }
                #pragma unroll
                for (int q = 0; q < 4; q++) {
                    int brow = wn + q * 16 + (lane & 15);
                    uint32_t r0, r1, r2, r3;
                    ldsm4(r0, r1, r2, r3, sw_addr(Bb, brow, kch));
                    #pragma unroll
                    for (int mi = 0; mi < 2; mi++) {
                        mma16816(acc[mi][q * 2 + 0], a[mi][0], a[mi][1], a[mi][2], a[mi][3], r0, r2);
                        mma16816(acc[mi][q * 2 + 1], a[mi][0], a[mi][1], a[mi][2], a[mi][3], r1, r3);
                    }
                }
            }
        }
    }

    // epilogue: c0,c1 -> (row t/4, col 2(t%4)); c2,c3 -> row+8
    float* O = (mat == 0) ? g_Q : (mat == 1) ? g_K : g_V;
    const int tq = lane >> 2, tr = lane & 3;
    #pragma unroll
    for (int mi = 0; mi < 2; mi++) {
        int r0 = tile * 128 + wm + mi * 16 + tq;
        #pragma unroll
        for (int nf = 0; nf < 8; nf++) {
            int col = wn + nf * 8 + tr * 2;
            if (r0 < N_NODES)
                *(float2*)&O[(size_t)r0 * OUT_F + col] = make_float2(acc[mi][nf][0], acc[mi][nf][1]);
            if (r0 + 8 < N_NODES)
                *(float2*)&O[(size_t)(r0 + 8) * OUT_F + col] = make_float2(acc[mi][nf][2], acc[mi][nf][3]);
        }
    }
}

// ---------------- CSR build -----------------
__global__ void k_count(const void* __restrict__ ei)
{
    int e = blockIdx.x * blockDim.x + threadIdx.x;
    if (e < N_EDGES) {
        int r = edge_at(ei, e);
        if ((unsigned)r < N_NODES) atomicAdd(&g_cnt[r], 1);
    }
}

__global__ __launch_bounds__(1024) void k_scan1()
{
    __shared__ int wsum[32];
    int i = blockIdx.x * 1024 + threadIdx.x;
    int v = (i < N_NODES) ? g_cnt[i] : 0;
    int lane = threadIdx.x & 31, w = threadIdx.x >> 5;

    int s = v;
    #pragma unroll
    for (int o = 1; o < 32; o <<= 1) {
        int t = __shfl_up_sync(0xffffffffu, s, o);
        if (lane >= o) s += t;
    }
    if (lane == 31) wsum[w] = s;
    __syncthreads();
    if (w == 0) {
        int t = wsum[lane];
        #pragma unroll
        for (int o = 1; o < 32; o <<= 1) {
            int u = __shfl_up_sync(0xffffffffu, t, o);
            if (lane >= o) t += u;
        }
        wsum[lane] = t;
    }
    __syncthreads();
    int excl = s - v + (w ? wsum[w - 1] : 0);
    if (i < N_NODES) g_off[i] = excl;
    if (threadIdx.x == 1023) g_bsum[blockIdx.x] = wsum[31];
}

__global__ void k_scan2()
{
    __shared__ int sm[128];
    int t = threadIdx.x;
    int v = (t < NB_SCAN) ? g_bsum[t] : 0;
    sm[t] = v;
    __syncthreads();
    for (int o = 1; o < 128; o <<= 1) {
        int u = (t >= o) ? sm[t - o] : 0;
        __syncthreads();
        sm[t] += u;
        __syncthreads();
    }
    if (t < NB_SCAN) g_bsum[t] = sm[t] - v;   // exclusive
    if (t == 127) g_off[N_NODES] = sm[127];
}

__global__ __launch_bounds__(1024) void k_scan3()
{
    int i = blockIdx.x * 1024 + threadIdx.x;
    if (i < N_NODES) {
        int o = g_off[i] + g_bsum[blockIdx.x];
        g_off[i] = o;
        g_cur[i] = o;
    }
}

__global__ void k_scatter(const void* __restrict__ ei)
{
    int e = blockIdx.x * blockDim.x + threadIdx.x;
    if (e < N_EDGES) {
        int r = edge_at(ei, e);
        int c = edge_at(ei, N_EDGES + e);
        if ((unsigned)r < N_NODES && (unsigned)c < N_NODES) {
            int p = atomicAdd(&g_cur[r], 1);
            g_src[p] = c;
        }
    }
}

// ---------------- per-node online-softmax aggregation -------------
// One warp per destination node; dual edge streams for 2x MLP.
__global__ __launch_bounds__(256) void k_aggregate(
    const float* __restrict__ D, float* __restrict__ out)
{
    int warp = (blockIdx.x * blockDim.x + threadIdx.x) >> 5;
    int lane = threadIdx.x & 31;
    if (warp >= N_NODES) return;
    const int r = warp;

    const int beg = g_off[r];
    const int end = g_off[r + 1];

    const float4 kv = *(const float4*)&g_K[(size_t)r * OUT_F + lane * 4];
    const float4 Dv = *(const float4*)&D[lane * 4];
    const float scale = 0.1767766952966369f;   // 1/sqrt(32)

    float  m0 = -CUDART_INF_F, sw0 = 0.f;
    float  m1 = -CUDART_INF_F, sw1 = 0.f;
    float4 A0 = make_float4(0.f, 0.f, 0.f, 0.f);
    float4 A1 = make_float4(0.f, 0.f, 0.f, 0.f);

    int e = beg;
    for (; e + 2 <= end; e += 2) {
        const int c0 = g_src[e];
        const int c1 = g_src[e + 1];
        const float4 q0 = *(const float4*)&g_Q[(size_t)c0 * OUT_F + lane * 4];
        const float4 v0 = *(const float4*)&g_V[(size_t)c0 * OUT_F + lane * 4];
        const float4 q1 = *(const float4*)&g_Q[(size_t)c1 * OUT_F + lane * 4];
        const float4 v1 = *(const float4*)&g_V[(size_t)c1 * OUT_F + lane * 4];

        float s0, s1;
        {
            float4 t;
            if (c0 == r) {
                t.x = kv.x * Dv.x * q0.x; t.y = kv.y * Dv.y * q0.y;
                t.z = kv.z * Dv.z * q0.z; t.w = kv.w * Dv.w * q0.w;
            } else {
                float dx = kv.x - q0.x, dy = kv.y - q0.y, dz = kv.z - q0.z, dw = kv.w - q0.w;
                t.x = dx * Dv.x * dx; t.y = dy * Dv.y * dy;
                t.z = dz * Dv.z * dz; t.w = dw * Dv.w * dw;
            }
            s0 = t.x + t.y + t.z + t.w;
        }
        {
            float4 t;
            if (c1 == r) {
                t.x = kv.x * Dv.x * q1.x; t.y = kv.y * Dv.y * q1.y;
                t.z = kv.z * Dv.z * q1.z; t.w = kv.w * Dv.w * q1.w;
            } else {
                float dx = kv.x - q1.x, dy = kv.y - q1.y, dz = kv.z - q1.z, dw = kv.w - q1.w;
                t.x = dx * Dv.x * dx; t.y = dy * Dv.y * dy;
                t.z = dz * Dv.z * dz; t.w = dw * Dv.w * dw;
            }
            s1 = t.x + t.y + t.z + t.w;
        }
        s0 += __shfl_xor_sync(0xffffffffu, s0, 1);
        s1 += __shfl_xor_sync(0xffffffffu, s1, 1);
        s0 += __shfl_xor_sync(0xffffffffu, s0, 2);
        s1 += __shfl_xor_sync(0xffffffffu, s1, 2);
        s0 += __shfl_xor_sync(0xffffffffu, s0, 4);
        s1 += __shfl_xor_sync(0xffffffffu, s1, 4);
        s0 *= scale; s1 *= scale;
        s0 = (s0 > 0.f) ? s0 : 0.2f * s0;
        s1 = (s1 > 0.f) ? s1 : 0.2f * s1;

        {
            float mn = fmaxf(m0, s0);
            float cr = __expf(m0 - mn), w = __expf(s0 - mn);
            sw0 = sw0 * cr + w;
            A0.x = A0.x * cr + w * v0.x; A0.y = A0.y * cr + w * v0.y;
            A0.z = A0.z * cr + w * v0.z; A0.w = A0.w * cr + w * v0.w;
            m0 = mn;
        }
        {
            float mn = fmaxf(m1, s1);
            float cr = __expf(m1 - mn), w = __expf(s1 - mn);
            sw1 = sw1 * cr + w;
            A1.x = A1.x * cr + w * v1.x; A1.y = A1.y * cr + w * v1.y;
            A1.z = A1.z * cr + w * v1.z; A1.w = A1.w * cr + w * v1.w;
            m1 = mn;
        }
    }
    if (e < end) {
        const int c = g_src[e];
        const float4 q = *(const float4*)&g_Q[(size_t)c * OUT_F + lane * 4];
        const float4 v = *(const float4*)&g_V[(size_t)c * OUT_F + lane * 4];
        float4 t;
        if (c == r) {
            t.x = kv.x * Dv.x * q.x; t.y = kv.y * Dv.y * q.y;
            t.z = kv.z * Dv.z * q.z; t.w = kv.w * Dv.w * q.w;
        } else {
            float dx = kv.x - q.x, dy = kv.y - q.y, dz = kv.z - q.z, dw = kv.w - q.w;
            t.x = dx * Dv.x * dx; t.y = dy * Dv.y * dy;
            t.z = dz * Dv.z * dz; t.w = dw * Dv.w * dw;
        }
        float s = t.x + t.y + t.z + t.w;
        s += __shfl_xor_sync(0xffffffffu, s, 1);
        s += __shfl_xor_sync(0xffffffffu, s, 2);
        s += __shfl_xor_sync(0xffffffffu, s, 4);
        s *= scale;
        s = (s > 0.f) ? s : 0.2f * s;
        float mn = fmaxf(m0, s);
        float cr = __expf(m0 - mn), w = __expf(s - mn);
        sw0 = sw0 * cr + w;
        A0.x = A0.x * cr + w * v.x; A0.y = A0.y * cr + w * v.y;
        A0.z = A0.z * cr + w * v.z; A0.w = A0.w * cr + w * v.w;
        m0 = mn;
    }

    // merge state1 into state0 (state1 nonempty implies state0 nonempty)
    if (sw1 != 0.f) {
        float mn = fmaxf(m0, m1);
        float c0 = __expf(m0 - mn), c1 = __expf(m1 - mn);
        sw0 = sw0 * c0 + sw1 * c1;
        A0.x = A0.x * c0 + A1.x * c1; A0.y = A0.y * c0 + A1.y * c1;
        A0.z = A0.z * c0 + A1.z * c1; A0.w = A0.w * c0 + A1.w * c1;
    }

    const float inv = 1.f / (sw0 + 1e-16f);
    float4 o = make_float4(A0.x * inv, A0.y * inv, A0.z * inv, A0.w * inv);
    *(float4*)&out[(size_t)r * OUT_F + lane * 4] = o;
}

// ---------------- launch -----------------
extern "C" void kernel_launch(void* const* d_in, const int* in_sizes, int n_in,
                              void* d_out, int out_size)
{
    const float *x = 0, *Wq = 0, *Wk = 0, *Wv = 0, *D = 0;
    const void  *ei = 0;
    int wcount = 0;
    for (int i = 0; i < n_in; i++) {
        long long sz = in_sizes[i];
        if (sz == (long long)N_NODES * IN_F) {
            x = (const float*)d_in[i];
        } else if (sz == (long long)2 * N_EDGES) {
            ei = d_in[i];
        } else if (sz == (long long)IN_F * OUT_F) {
            if (wcount == 0)      Wq = (const float*)d_in[i];
            else if (wcount == 1) Wk = (const float*)d_in[i];
            else                  Wv = (const float*)d_in[i];
            wcount++;
        } else if (sz == OUT_F) {
            D = (const float*)d_in[i];
        }
    }
    float* out = (float*)d_out;

    const int SMEM_DYN = 65536;
    cudaFuncSetAttribute(qkv_hmma, cudaFuncAttributeMaxDynamicSharedMemorySize, SMEM_DYN);

    k_wconv<<<3, 128>>>(Wq, Wk, Wv);                          // 0
    k_zero<<<(N_NODES + 255) / 256, 256>>>(ei);               // 1
    k_count<<<(N_EDGES + 255) / 256, 256>>>(ei);              // 2
    dim3 gg(NTILES, 3);
    qkv_hmma<<<gg, 256, SMEM_DYN>>>(x);                       // 3  <- hoping ncu lands here
    k_scan1<<<NB_SCAN, 1024>>>();                             // 4
    k_scan2<<<1, 128>>>();                                    // 5
    k_scan3<<<NB_SCAN, 1024>>>();                             // 6
    k_scatter<<<(N_EDGES + 255) / 256, 256>>>(ei);            // 7
    k_aggregate<<<(N_NODES * 32 + 255) / 256, 256>>>(D, out); // 8
}

// round 11
// speedup vs baseline: 1.8651x; 1.1708x over previous
#include <cuda_runtime.h>
#include <cuda_bf16.h>
#include <cuda_fp16.h>
#include <math_constants.h>
#include <cstdint>

#define N_NODES 100000
#define N_EDGES 1600000
#define IN_F    128
#define OUT_F   128     // HEADS * D_K = 4 * 32
#define NB_SCAN ((N_NODES + 1023) / 1024)   // 98
#define NTILES  ((N_NODES + 127) / 128)     // 782

// ---------------- scratch (no allocations allowed) ----------------
__device__ float  g_Q[N_NODES * OUT_F];
__device__ float  g_K[N_NODES * OUT_F];
__device__ __half g_Vh[N_NODES * OUT_F];    // V gathered in fp16 (linear term only)
__device__ int    g_cnt[N_NODES];
__device__ int    g_off[N_NODES + 1];
__device__ int    g_cur[N_NODES];
__device__ int    g_src[N_EDGES];
__device__ int    g_bsum[128];
__device__ int    g_is64;
// bf16 hi/lo weight images, row-major [row][128]
__device__ __nv_bfloat16 g_Wb[3][2][OUT_F * IN_F];

// ---------------- mma.sync helpers (base sm_103 legal) ----------------
__device__ __forceinline__ uint32_t smem_u32(const void* p)
{
    uint32_t a;
    asm("{ .reg .u64 t; cvta.to.shared.u64 t, %1; cvt.u32.u64 %0, t; }"
        : "=r"(a) : "l"(p));
    return a;
}
__device__ __forceinline__ void ldsm4(uint32_t& r0, uint32_t& r1, uint32_t& r2,
                                      uint32_t& r3, uint32_t addr)
{
    asm volatile("ldmatrix.sync.aligned.m8n8.x4.shared.b16 {%0,%1,%2,%3}, [%4];"
                 : "=r"(r0), "=r"(r1), "=r"(r2), "=r"(r3) : "r"(addr));
}
__device__ __forceinline__ void mma16816(float* c,
                                         uint32_t a0, uint32_t a1, uint32_t a2, uint32_t a3,
                                         uint32_t b0, uint32_t b1)
{
    asm volatile("mma.sync.aligned.m16n8k16.row.col.f32.bf16.bf16.f32 "
                 "{%0,%1,%2,%3}, {%4,%5,%6,%7}, {%8,%9}, {%0,%1,%2,%3};"
                 : "+f"(c[0]), "+f"(c[1]), "+f"(c[2]), "+f"(c[3])
                 : "r"(a0), "r"(a1), "r"(a2), "r"(a3), "r"(b0), "r"(b1));
}
// swizzled smem addr: 128B rows of 8x16B chunks, chunk XOR (row&7)
__device__ __forceinline__ uint32_t sw_addr(uint32_t base, int row, int kchunk)
{
    return base + (uint32_t)(row << 7) + (uint32_t)(((kchunk ^ (row & 7)) & 7) << 4);
}

// Edge accessor: ei is either int64[2, E] or int32[2, E]; g_is64 selects.
__device__ __forceinline__ int edge_at(const void* ei, int idx)
{
    if (g_is64) return (int)((const long long*)ei)[idx];
    return ((const int*)ei)[idx];
}

// zero counters + detect edge dtype (thread 0)
__global__ void k_zero(const void* __restrict__ ei)
{
    int i = blockIdx.x * blockDim.x + threadIdx.x;
    if (i < N_NODES) g_cnt[i] = 0;
    if (i == 0) {
        const long long* p = (const long long*)ei;
        bool ok = true;
        #pragma unroll
        for (int k = 0; k < 8; k++) {
            long long v = p[k];
            if (v < 0 || v >= N_NODES) ok = false;
        }
        g_is64 = ok ? 1 : 0;
    }
}

// ---------------- bf16 hi/lo weight pre-conversion ----------------
__global__ void k_wconv(const float* __restrict__ Wq,
                        const float* __restrict__ Wk,
                        const float* __restrict__ Wv)
{
    int mat = blockIdx.x;
    const float* W = (mat == 0) ? Wq : (mat == 1) ? Wk : Wv;
    int row = threadIdx.x;            // output-feature 0..127
    #pragma unroll 4
    for (int c8 = 0; c8 < 16; c8++) {
        union { __nv_bfloat16 b[8]; uint4 v; } H, L;
        #pragma unroll
        for (int j = 0; j < 8; j++) {
            float f = W[row * IN_F + c8 * 8 + j];
            __nv_bfloat16 h = __float2bfloat16(f);
            H.b[j] = h;
            L.b[j] = __float2bfloat16(f - __bfloat162float(h));
        }
        *(uint4*)&g_Wb[mat][0][row * IN_F + c8 * 8] = H.v;
        *(uint4*)&g_Wb[mat][1][row * IN_F + c8 * 8] = L.v;
    }
}

// ---------------- HMMA QKV GEMM (x converted in-kernel) ----------------
// grid (NTILES, 3), 256 threads (8 warps, 32x64 warp tiles).
// O = X @ W^T, 3-term bf16 split (hi*hi + hi*lo + lo*hi), fp32 accum.
// Fragments shared across terms: 12 ldsm4 per k16 instead of 18.
__global__ __launch_bounds__(256, 2) void qkv_hmma(const float* __restrict__ xp)
{
    extern __shared__ __align__(1024) unsigned char dsm[];
    const uint32_t sbase = smem_u32(dsm);
    const uint32_t Ah = sbase, Al = sbase + 16384, Bh = sbase + 32768, Bl = sbase + 49152;

    const int tile = blockIdx.x, mat = blockIdx.y;
    const int tid = threadIdx.x, wid = tid >> 5, lane = tid & 31;
    const int wm = (wid & 3) * 32;        // warp M offset
    const int wn = (wid >> 2) * 64;       // warp N offset

    const __nv_bfloat16* wh = g_Wb[mat][0];
    const __nv_bfloat16* wl = g_Wb[mat][1];

    float acc[2][8][4];
    #pragma unroll
    for (int mi = 0; mi < 2; mi++)
        #pragma unroll
        for (int nf = 0; nf < 8; nf++)
            #pragma unroll
            for (int j = 0; j < 4; j++) acc[mi][nf][j] = 0.f;

    for (int kc = 0; kc < IN_F; kc += 64) {
        if (kc) __syncthreads();
        // A: read x fp32, split into bf16 hi/lo, store swizzled
        // B: copy pre-baked bf16 weight rows, store swizzled
        #pragma unroll
        for (int i = tid; i < 1024; i += 256) {
            int row = i >> 3, ch = i & 7;
            uint32_t dst = (uint32_t)(row << 7) + (uint32_t)(((ch ^ (row & 7)) & 7) << 4);
            int gr = tile * 128 + row;
            union { __nv_bfloat16 b[8]; uint4 v; } H, L;
            if (gr < N_NODES) {
                const float4 f0 = *(const float4*)&xp[(size_t)gr * IN_F + kc + ch * 8 + 0];
                const float4 f1 = *(const float4*)&xp[(size_t)gr * IN_F + kc + ch * 8 + 4];
                float fs[8] = {f0.x,f0.y,f0.z,f0.w,f1.x,f1.y,f1.z,f1.w};
                #pragma unroll
                for (int j = 0; j < 8; j++) {
                    __nv_bfloat16 h = __float2bfloat16(fs[j]);
                    H.b[j] = h;
                    L.b[j] = __float2bfloat16(fs[j] - __bfloat162float(h));
                }
            } else {
                H.v = make_uint4(0,0,0,0);
                L.v = make_uint4(0,0,0,0);
            }
            *(uint4*)(dsm + (Ah - sbase) + dst) = H.v;
            *(uint4*)(dsm + (Al - sbase) + dst) = L.v;
            size_t wsrc = (size_t)row * IN_F + kc + ch * 8;
            *(uint4*)(dsm + (Bh - sbase) + dst) = *(const uint4*)&wh[wsrc];
            *(uint4*)(dsm + (Bl - sbase) + dst) = *(const uint4*)&wl[wsrc];
        }
        __syncthreads();

        #pragma unroll
        for (int kl = 0; kl < 64; kl += 16) {
            const int kch = (kl >> 3) + (lane >> 4);
            uint32_t ah[2][4], al[2][4];
            #pragma unroll
            for (int mi = 0; mi < 2; mi++) {
                int arow = wm + mi * 16 + (lane & 15);
                ldsm4(ah[mi][0], ah[mi][1], ah[mi][2], ah[mi][3], sw_addr(Ah, arow, kch));
                ldsm4(al[mi][0], al[mi][1], al[mi][2], al[mi][3], sw_addr(Al, arow, kch));
            }
            #pragma unroll
            for (int q = 0; q < 4; q++) {
                int brow = wn + q * 16 + (lane & 15);
                uint32_t h0, h1, h2, h3, l0, l1, l2, l3;
                ldsm4(h0, h1, h2, h3, sw_addr(Bh, brow, kch));
                ldsm4(l0, l1, l2, l3, sw_addr(Bl, brow, kch));
                #pragma unroll
                for (int mi = 0; mi < 2; mi++) {
                    // hi*hi
                    mma16816(acc[mi][q * 2 + 0], ah[mi][0], ah[mi][1], ah[mi][2], ah[mi][3], h0, h2);
                    mma16816(acc[mi][q * 2 + 1], ah[mi][0], ah[mi][1], ah[mi][2], ah[mi][3], h1, h3);
                    // hi*lo
                    mma16816(acc[mi][q * 2 + 0], ah[mi][0], ah[mi][1], ah[mi][2], ah[mi][3], l0, l2);
                    mma16816(acc[mi][q * 2 + 1], ah[mi][0], ah[mi][1], ah[mi][2], ah[mi][3], l1, l3);
                    // lo*hi
                    mma16816(acc[mi][q * 2 + 0], al[mi][0], al[mi][1], al[mi][2], al[mi][3], h0, h2);
                    mma16816(acc[mi][q * 2 + 1], al[mi][0], al[mi][1], al[mi][2], al[mi][3], h1, h3);
                }
            }
        }
    }

    // epilogue: c0,c1 -> (row t/4, col 2(t%4)); c2,c3 -> row+8
    const int tq = lane >> 2, tr = lane & 3;
    #pragma unroll
    for (int mi = 0; mi < 2; mi++) {
        int r0 = tile * 128 + wm + mi * 16 + tq;
        #pragma unroll
        for (int nf = 0; nf < 8; nf++) {
            int col = wn + nf * 8 + tr * 2;
            if (mat == 2) {
                if (r0 < N_NODES)
                    *(__half2*)&g_Vh[(size_t)r0 * OUT_F + col] =
                        __floats2half2_rn(acc[mi][nf][0], acc[mi][nf][1]);
                if (r0 + 8 < N_NODES)
                    *(__half2*)&g_Vh[(size_t)(r0 + 8) * OUT_F + col] =
                        __floats2half2_rn(acc[mi][nf][2], acc[mi][nf][3]);
            } else {
                float* O = (mat == 0) ? g_Q : g_K;
                if (r0 < N_NODES)
                    *(float2*)&O[(size_t)r0 * OUT_F + col] = make_float2(acc[mi][nf][0], acc[mi][nf][1]);
                if (r0 + 8 < N_NODES)
                    *(float2*)&O[(size_t)(r0 + 8) * OUT_F + col] = make_float2(acc[mi][nf][2], acc[mi][nf][3]);
            }
        }
    }
}

// ---------------- CSR build -----------------
// 2 edges per thread, vectorized loads
__global__ void k_count(const void* __restrict__ ei)
{
    int e = (blockIdx.x * blockDim.x + threadIdx.x) * 2;
    if (e < N_EDGES) {
        int r0, r1;
        if (g_is64) {
            longlong2 p = *(const longlong2*)((const long long*)ei + e);
            r0 = (int)p.x; r1 = (int)p.y;
        } else {
            int2 p = *(const int2*)((const int*)ei + e);
            r0 = p.x; r1 = p.y;
        }
        if ((unsigned)r0 < N_NODES) atomicAdd(&g_cnt[r0], 1);
        if ((unsigned)r1 < N_NODES) atomicAdd(&g_cnt[r1], 1);
    }
}

__global__ __launch_bounds__(1024) void k_scan1()
{
    __shared__ int wsum[32];
    int i = blockIdx.x * 1024 + threadIdx.x;
    int v = (i < N_NODES) ? g_cnt[i] : 0;
    int lane = threadIdx.x & 31, w = threadIdx.x >> 5;

    int s = v;
    #pragma unroll
    for (int o = 1; o < 32; o <<= 1) {
        int t = __shfl_up_sync(0xffffffffu, s, o);
        if (lane >= o) s += t;
    }
    if (lane == 31) wsum[w] = s;
    __syncthreads();
    if (w == 0) {
        int t = wsum[lane];
        #pragma unroll
        for (int o = 1; o < 32; o <<= 1) {
            int u = __shfl_up_sync(0xffffffffu, t, o);
            if (lane >= o) t += u;
        }
        wsum[lane] = t;
    }
    __syncthreads();
    int excl = s - v + (w ? wsum[w - 1] : 0);
    if (i < N_NODES) g_off[i] = excl;
    if (threadIdx.x == 1023) g_bsum[blockIdx.x] = wsum[31];
}

__global__ void k_scan2()
{
    __shared__ int sm[128];
    int t = threadIdx.x;
    int v = (t < NB_SCAN) ? g_bsum[t] : 0;
    sm[t] = v;
    __syncthreads();
    for (int o = 1; o < 128; o <<= 1) {
        int u = (t >= o) ? sm[t - o] : 0;
        __syncthreads();
        sm[t] += u;
        __syncthreads();
    }
    if (t < NB_SCAN) g_bsum[t] = sm[t] - v;   // exclusive
    if (t == 127) g_off[N_NODES] = sm[127];
}

__global__ __launch_bounds__(1024) void k_scan3()
{
    int i = blockIdx.x * 1024 + threadIdx.x;
    if (i < N_NODES) {
        int o = g_off[i] + g_bsum[blockIdx.x];
        g_off[i] = o;
        g_cur[i] = o;
    }
}

__global__ void k_scatter(const void* __restrict__ ei)
{
    int e = (blockIdx.x * blockDim.x + threadIdx.x) * 2;
    if (e < N_EDGES) {
        int r0, r1, c0, c1;
        if (g_is64) {
            longlong2 pr = *(const longlong2*)((const long long*)ei + e);
            longlong2 pc = *(const longlong2*)((const long long*)ei + N_EDGES + e);
            r0 = (int)pr.x; r1 = (int)pr.y; c0 = (int)pc.x; c1 = (int)pc.y;
        } else {
            int2 pr = *(const int2*)((const int*)ei + e);
            int2 pc = *(const int2*)((const int*)ei + N_EDGES + e);
            r0 = pr.x; r1 = pr.y; c0 = pc.x; c1 = pc.y;
        }
        if ((unsigned)r0 < N_NODES && (unsigned)c0 < N_NODES) {
            int p = atomicAdd(&g_cur[r0], 1);
            g_src[p] = c0;
        }
        if ((unsigned)r1 < N_NODES && (unsigned)c1 < N_NODES) {
            int p = atomicAdd(&g_cur[r1], 1);
            g_src[p] = c1;
        }
    }
}

// ---------------- per-node online-softmax aggregation -------------
// One warp per destination node; dual edge streams for 2x MLP.
// Q/K fp32 (score precision), V fp16 (linear term).
__global__ __launch_bounds__(256) void k_aggregate(
    const float* __restrict__ D, float* __restrict__ out)
{
    int warp = (blockIdx.x * blockDim.x + threadIdx.x) >> 5;
    int lane = threadIdx.x & 31;
    if (warp >= N_NODES) return;
    const int r = warp;

    const int beg = g_off[r];
    const int end = g_off[r + 1];

    const float4 kv = *(const float4*)&g_K[(size_t)r * OUT_F + lane * 4];
    const float4 Dv = *(const float4*)&D[lane * 4];
    const float scale = 0.1767766952966369f;   // 1/sqrt(32)

    float  m0 = -CUDART_INF_F, sw0 = 0.f;
    float  m1 = -CUDART_INF_F, sw1 = 0.f;
    float4 A0 = make_float4(0.f, 0.f, 0.f, 0.f);
    float4 A1 = make_float4(0.f, 0.f, 0.f, 0.f);

    int e = beg;
    for (; e + 2 <= end; e += 2) {
        const int c0 = g_src[e];
        const int c1 = g_src[e + 1];
        const float4 q0 = *(const float4*)&g_Q[(size_t)c0 * OUT_F + lane * 4];
        const uint2  u0 = *(const uint2*)&g_Vh[(size_t)c0 * OUT_F + lane * 4];
        const float4 q1 = *(const float4*)&g_Q[(size_t)c1 * OUT_F + lane * 4];
        const uint2  u1 = *(const uint2*)&g_Vh[(size_t)c1 * OUT_F + lane * 4];
        const float2 v0a = __half22float2(*(const __half2*)&u0.x);
        const float2 v0b = __half22float2(*(const __half2*)&u0.y);
        const float2 v1a = __half22float2(*(const __half2*)&u1.x);
        const float2 v1b = __half22float2(*(const __half2*)&u1.y);

        float s0, s1;
        {
            float4 t;
            if (c0 == r) {
                t.x = kv.x * Dv.x * q0.x; t.y = kv.y * Dv.y * q0.y;
                t.z = kv.z * Dv.z * q0.z; t.w = kv.w * Dv.w * q0.w;
            } else {
                float dx = kv.x - q0.x, dy = kv.y - q0.y, dz = kv.z - q0.z, dw = kv.w - q0.w;
                t.x = dx * Dv.x * dx; t.y = dy * Dv.y * dy;
                t.z = dz * Dv.z * dz; t.w = dw * Dv.w * dw;
            }
            s0 = t.x + t.y + t.z + t.w;
        }
        {
            float4 t;
            if (c1 == r) {
                t.x = kv.x * Dv.x * q1.x; t.y = kv.y * Dv.y * q1.y;
                t.z = kv.z * Dv.z * q1.z; t.w = kv.w * Dv.w * q1.w;
            } else {
                float dx = kv.x - q1.x, dy = kv.y - q1.y, dz = kv.z - q1.z, dw = kv.w - q1.w;
                t.x = dx * Dv.x * dx; t.y = dy * Dv.y * dy;
                t.z = dz * Dv.z * dz; t.w = dw * Dv.w * dw;
            }
            s1 = t.x + t.y + t.z + t.w;
        }
        s0 += __shfl_xor_sync(0xffffffffu, s0, 1);
        s1 += __shfl_xor_sync(0xffffffffu, s1, 1);
        s0 += __shfl_xor_sync(0xffffffffu, s0, 2);
        s1 += __shfl_xor_sync(0xffffffffu, s1, 2);
        s0 += __shfl_xor_sync(0xffffffffu, s0, 4);
        s1 += __shfl_xor_sync(0xffffffffu, s1, 4);
        s0 *= scale; s1 *= scale;
        s0 = (s0 > 0.f) ? s0 : 0.2f * s0;
        s1 = (s1 > 0.f) ? s1 : 0.2f * s1;

        {
            float mn = fmaxf(m0, s0);
            float cr = __expf(m0 - mn), w = __expf(s0 - mn);
            sw0 = sw0 * cr + w;
            A0.x = A0.x * cr + w * v0a.x; A0.y = A0.y * cr + w * v0a.y;
            A0.z = A0.z * cr + w * v0b.x; A0.w = A0.w * cr + w * v0b.y;
            m0 = mn;
        }
        {
            float mn = fmaxf(m1, s1);
            float cr = __expf(m1 - mn), w = __expf(s1 - mn);
            sw1 = sw1 * cr + w;
            A1.x = A1.x * cr + w * v1a.x; A1.y = A1.y * cr + w * v1a.y;
            A1.z = A1.z * cr + w * v1b.x; A1.w = A1.w * cr + w * v1b.y;
            m1 = mn;
        }
    }
    if (e < end) {
        const int c = g_src[e];
        const float4 q = *(const float4*)&g_Q[(size_t)c * OUT_F + lane * 4];
        const uint2  u = *(const uint2*)&g_Vh[(size_t)c * OUT_F + lane * 4];
        const float2 va = __half22float2(*(const __half2*)&u.x);
        const float2 vb = __half22float2(*(const __half2*)&u.y);
        float4 t;
        if (c == r) {
            t.x = kv.x * Dv.x * q.x; t.y = kv.y * Dv.y * q.y;
            t.z = kv.z * Dv.z * q.z; t.w = kv.w * Dv.w * q.w;
        } else {
            float dx = kv.x - q.x, dy = kv.y - q.y, dz = kv.z - q.z, dw = kv.w - q.w;
            t.x = dx * Dv.x * dx; t.y = dy * Dv.y * dy;
            t.z = dz * Dv.z * dz; t.w = dw * Dv.w * dw;
        }
        float s = t.x + t.y + t.z + t.w;
        s += __shfl_xor_sync(0xffffffffu, s, 1);
        s += __shfl_xor_sync(0xffffffffu, s, 2);
        s += __shfl_xor_sync(0xffffffffu, s, 4);
        s *= scale;
        s = (s > 0.f) ? s : 0.2f * s;
        float mn = fmaxf(m0, s);
        float cr = __expf(m0 - mn), w = __expf(s - mn);
        sw0 = sw0 * cr + w;
        A0.x = A0.x * cr + w * va.x; A0.y = A0.y * cr + w * va.y;
        A0.z = A0.z * cr + w * vb.x; A0.w = A0.w * cr + w * vb.y;
        m0 = mn;
    }

    // merge state1 into state0 (state1 nonempty implies state0 nonempty)
    if (sw1 != 0.f) {
        float mn = fmaxf(m0, m1);
        float c0 = __expf(m0 - mn), c1 = __expf(m1 - mn);
        sw0 = sw0 * c0 + sw1 * c1;
        A0.x = A0.x * c0 + A1.x * c1; A0.y = A0.y * c0 + A1.y * c1;
        A0.z = A0.z * c0 + A1.z * c1; A0.w = A0.w * c0 + A1.w * c1;
    }

    const float inv = 1.f / (sw0 + 1e-16f);
    float4 o = make_float4(A0.x * inv, A0.y * inv, A0.z * inv, A0.w * inv);
    *(float4*)&out[(size_t)r * OUT_F + lane * 4] = o;
}

// ---------------- launch -----------------
extern "C" void kernel_launch(void* const* d_in, const int* in_sizes, int n_in,
                              void* d_out, int out_size)
{
    const float *x = 0, *Wq = 0, *Wk = 0, *Wv = 0, *D = 0;
    const void  *ei = 0;
    int wcount = 0;
    for (int i = 0; i < n_in; i++) {
        long long sz = in_sizes[i];
        if (sz == (long long)N_NODES * IN_F) {
            x = (const float*)d_in[i];
        } else if (sz == (long long)2 * N_EDGES) {
            ei = d_in[i];
        } else if (sz == (long long)IN_F * OUT_F) {
            if (wcount == 0)      Wq = (const float*)d_in[i];
            else if (wcount == 1) Wk = (const float*)d_in[i];
            else                  Wv = (const float*)d_in[i];
            wcount++;
        } else if (sz == OUT_F) {
            D = (const float*)d_in[i];
        }
    }
    float* out = (float*)d_out;

    const int SMEM_DYN = 65536;
    cudaFuncSetAttribute(qkv_hmma, cudaFuncAttributeMaxDynamicSharedMemorySize, SMEM_DYN);

    k_wconv<<<3, 128>>>(Wq, Wk, Wv);                          // 0
    k_zero<<<(N_NODES + 255) / 256, 256>>>(ei);               // 1
    k_count<<<(N_EDGES / 2 + 255) / 256, 256>>>(ei);          // 2
    dim3 gg(NTILES, 3);
    qkv_hmma<<<gg, 256, SMEM_DYN>>>(x);                       // 3
    k_scan1<<<NB_SCAN, 1024>>>();                             // 4
    k_scan2<<<1, 128>>>();                                    // 5
    k_scan3<<<NB_SCAN, 1024>>>();                             // 6
    k_scatter<<<(N_EDGES / 2 + 255) / 256, 256>>>(ei);        // 7
    k_aggregate<<<(N_NODES * 32 + 255) / 256, 256>>>(D, out); // 8
}

// round 13
// speedup vs baseline: 2.0759x; 1.1131x over previous
#include <cuda_runtime.h>
#include <cuda_fp16.h>
#include <math_constants.h>
#include <cstdint>

#define N_NODES 100000
#define N_EDGES 1600000
#define IN_F    128
#define OUT_F   128     // HEADS * D_K = 4 * 32
#define NB_SCAN ((N_NODES + 1023) / 1024)   // 98
#define NTILES  ((N_NODES + 127) / 128)     // 782

// ---------------- scratch (no allocations allowed) ----------------
__device__ float  g_Q[N_NODES * OUT_F];
__device__ float  g_K[N_NODES * OUT_F];
__device__ __half g_Vh[N_NODES * OUT_F];    // V gathered in fp16 (linear term only)
__device__ int    g_cnt[N_NODES];
__device__ int    g_off[N_NODES + 1];
__device__ int    g_cur[N_NODES];
__device__ int    g_src[N_EDGES];
__device__ int    g_bsum[128];
__device__ int    g_is64;
// single-fp16 weight images, row-major [out_feature][128]
__device__ __half g_Wh[3][OUT_F * IN_F];

// ---------------- mma.sync helpers (base sm_103 legal) ----------------
__device__ __forceinline__ uint32_t smem_u32(const void* p)
{
    uint32_t a;
    asm("{ .reg .u64 t; cvta.to.shared.u64 t, %1; cvt.u32.u64 %0, t; }"
        : "=r"(a) : "l"(p));
    return a;
}
__device__ __forceinline__ void ldsm4(uint32_t& r0, uint32_t& r1, uint32_t& r2,
                                      uint32_t& r3, uint32_t addr)
{
    asm volatile("ldmatrix.sync.aligned.m8n8.x4.shared.b16 {%0,%1,%2,%3}, [%4];"
                 : "=r"(r0), "=r"(r1), "=r"(r2), "=r"(r3) : "r"(addr));
}
__device__ __forceinline__ void mma16816(float* c,
                                         uint32_t a0, uint32_t a1, uint32_t a2, uint32_t a3,
                                         uint32_t b0, uint32_t b1)
{
    asm volatile("mma.sync.aligned.m16n8k16.row.col.f32.f16.f16.f32 "
                 "{%0,%1,%2,%3}, {%4,%5,%6,%7}, {%8,%9}, {%0,%1,%2,%3};"
                 : "+f"(c[0]), "+f"(c[1]), "+f"(c[2]), "+f"(c[3])
                 : "r"(a0), "r"(a1), "r"(a2), "r"(a3), "r"(b0), "r"(b1));
}
// 256B-row swizzled chunk offset: 16 chunks of 16B, low-3 chunk bits XOR row&7
__device__ __forceinline__ uint32_t sw256(int row, int ch)
{
    return (uint32_t)(row << 8) + (uint32_t)(((ch & 8) | ((ch & 7) ^ (row & 7))) << 4);
}

// Edge accessor: ei is either int64[2, E] or int32[2, E]; g_is64 selects.
__device__ __forceinline__ int edge_at(const void* ei, int idx)
{
    if (g_is64) return (int)((const long long*)ei)[idx];
    return ((const int*)ei)[idx];
}

// zero counters + detect edge dtype (thread 0)
__global__ void k_zero(const void* __restrict__ ei)
{
    int i = blockIdx.x * blockDim.x + threadIdx.x;
    if (i < N_NODES) g_cnt[i] = 0;
    if (i == 0) {
        const long long* p = (const long long*)ei;
        bool ok = true;
        #pragma unroll
        for (int k = 0; k < 8; k++) {
            long long v = p[k];
            if (v < 0 || v >= N_NODES) ok = false;
        }
        g_is64 = ok ? 1 : 0;
    }
}

// ---------------- fp16 weight pre-conversion ----------------
__global__ void k_wconv(const float* __restrict__ Wq,
                        const float* __restrict__ Wk,
                        const float* __restrict__ Wv)
{
    int mat = blockIdx.x;
    const float* W = (mat == 0) ? Wq : (mat == 1) ? Wk : Wv;
    int row = threadIdx.x;            // output-feature 0..127
    #pragma unroll 4
    for (int c8 = 0; c8 < 16; c8++) {
        union { __half b[8]; uint4 v; } H;
        #pragma unroll
        for (int j = 0; j < 8; j++)
            H.b[j] = __float2half_rn(W[row * IN_F + c8 * 8 + j]);
        *(uint4*)&g_Wh[mat][row * IN_F + c8 * 8] = H.v;
    }
}

// ---------------- HMMA QKV GEMM ----------------
// grid (NTILES), 256 threads (8 warps, 32x64 warp tiles).
// A = x split into fp16 hi+lo (once per tile, full K in smem, 64KB);
// B = W single fp16 (32KB, reloaded per mat). 2-term: (Ahi + Alo) @ B.
// Per k16-step: 8 ldsm4 + 32 MMA (was 12/48 with bf16 3-term).
__global__ __launch_bounds__(256, 2) void qkv_hmma(const float* __restrict__ xp)
{
    extern __shared__ __align__(1024) unsigned char dsm[];
    const uint32_t sbase = smem_u32(dsm);
    const uint32_t Ah = sbase, Al = sbase + 32768, Bs = sbase + 65536;

    const int tile = blockIdx.x;
    const int tid = threadIdx.x, wid = tid >> 5, lane = tid & 31;
    const int wm = (wid & 3) * 32;        // warp M offset
    const int wn = (wid >> 2) * 64;       // warp N offset

    // ---- A: read x fp32 once, split fp16 hi/lo, store swizzled (full K) ----
    #pragma unroll
    for (int i = tid; i < 2048; i += 256) {
        int row = i >> 4, ch = i & 15;
        uint32_t dst = sw256(row, ch);
        int gr = tile * 128 + row;
        union { __half b[8]; uint4 v; } H, L;
        if (gr < N_NODES) {
            const float4 f0 = *(const float4*)&xp[(size_t)gr * IN_F + ch * 8 + 0];
            const float4 f1 = *(const float4*)&xp[(size_t)gr * IN_F + ch * 8 + 4];
            float fs[8] = {f0.x,f0.y,f0.z,f0.w,f1.x,f1.y,f1.z,f1.w};
            #pragma unroll
            for (int j = 0; j < 8; j++) {
                __half h = __float2half_rn(fs[j]);
                H.b[j] = h;
                L.b[j] = __float2half_rn(fs[j] - __half2float(h));
            }
        } else {
            H.v = make_uint4(0,0,0,0);
            L.v = make_uint4(0,0,0,0);
        }
        *(uint4*)(dsm + (Ah - sbase) + dst) = H.v;
        *(uint4*)(dsm + (Al - sbase) + dst) = L.v;
    }
    __syncthreads();

    for (int mat = 0; mat < 3; mat++) {
        // ---- B: copy fp16 weights swizzled ----
        const __half* wsrc = g_Wh[mat];
        #pragma unroll
        for (int i = tid; i < 2048; i += 256) {
            int row = i >> 4, ch = i & 15;
            *(uint4*)(dsm + (Bs - sbase) + sw256(row, ch)) =
                *(const uint4*)&wsrc[(size_t)row * IN_F + ch * 8];
        }
        __syncthreads();

        float acc[2][8][4];
        #pragma unroll
        for (int mi = 0; mi < 2; mi++)
            #pragma unroll
            for (int nf = 0; nf < 8; nf++)
                #pragma unroll
                for (int j = 0; j < 4; j++) acc[mi][nf][j] = 0.f;

        #pragma unroll
        for (int k16 = 0; k16 < 8; k16++) {
            const int base8 = (k16 >> 2) << 3;
            const int c3 = ((k16 & 3) << 1) + (lane >> 4);
            uint32_t ah[2][4], al[2][4];
            #pragma unroll
            for (int mi = 0; mi < 2; mi++) {
                int arow = wm + mi * 16 + (lane & 15);
                uint32_t co = (uint32_t)((base8 + (c3 ^ (arow & 7))) << 4) + (uint32_t)(arow << 8);
                ldsm4(ah[mi][0], ah[mi][1], ah[mi][2], ah[mi][3], Ah + co);
                ldsm4(al[mi][0], al[mi][1], al[mi][2], al[mi][3], Al + co);
            }
            #pragma unroll
            for (int q = 0; q < 4; q++) {
                int brow = wn + q * 16 + (lane & 15);
                uint32_t b0, b1, b2, b3;
                ldsm4(b0, b1, b2, b3,
                      Bs + (uint32_t)(brow << 8) + (uint32_t)((base8 + (c3 ^ (brow & 7))) << 4));
                #pragma unroll
                for (int mi = 0; mi < 2; mi++) {
                    mma16816(acc[mi][q * 2 + 0], ah[mi][0], ah[mi][1], ah[mi][2], ah[mi][3], b0, b2);
                    mma16816(acc[mi][q * 2 + 1], ah[mi][0], ah[mi][1], ah[mi][2], ah[mi][3], b1, b3);
                    mma16816(acc[mi][q * 2 + 0], al[mi][0], al[mi][1], al[mi][2], al[mi][3], b0, b2);
                    mma16816(acc[mi][q * 2 + 1], al[mi][0], al[mi][1], al[mi][2], al[mi][3], b1, b3);
                }
            }
        }
        __syncthreads();   // all MMAs done before B is overwritten next mat

        // ---- epilogue: c0,c1 -> (row t/4, col 2(t%4)); c2,c3 -> row+8 ----
        const int tq = lane >> 2, tr = lane & 3;
        #pragma unroll
        for (int mi = 0; mi < 2; mi++) {
            int r0 = tile * 128 + wm + mi * 16 + tq;
            #pragma unroll
            for (int nf = 0; nf < 8; nf++) {
                int col = wn + nf * 8 + tr * 2;
                if (mat == 2) {
                    if (r0 < N_NODES)
                        *(__half2*)&g_Vh[(size_t)r0 * OUT_F + col] =
                            __floats2half2_rn(acc[mi][nf][0], acc[mi][nf][1]);
                    if (r0 + 8 < N_NODES)
                        *(__half2*)&g_Vh[(size_t)(r0 + 8) * OUT_F + col] =
                            __floats2half2_rn(acc[mi][nf][2], acc[mi][nf][3]);
                } else {
                    float* O = (mat == 0) ? g_Q : g_K;
                    if (r0 < N_NODES)
                        *(float2*)&O[(size_t)r0 * OUT_F + col] = make_float2(acc[mi][nf][0], acc[mi][nf][1]);
                    if (r0 + 8 < N_NODES)
                        *(float2*)&O[(size_t)(r0 + 8) * OUT_F + col] = make_float2(acc[mi][nf][2], acc[mi][nf][3]);
                }
            }
        }
    }
}

// ---------------- CSR build -----------------
// 2 edges per thread, vectorized loads
__global__ void k_count(const void* __restrict__ ei)
{
    int e = (blockIdx.x * blockDim.x + threadIdx.x) * 2;
    if (e < N_EDGES) {
        int r0, r1;
        if (g_is64) {
            longlong2 p = *(const longlong2*)((const long long*)ei + e);
            r0 = (int)p.x; r1 = (int)p.y;
        } else {
            int2 p = *(const int2*)((const int*)ei + e);
            r0 = p.x; r1 = p.y;
        }
        if ((unsigned)r0 < N_NODES) atomicAdd(&g_cnt[r0], 1);
        if ((unsigned)r1 < N_NODES) atomicAdd(&g_cnt[r1], 1);
    }
}

__global__ __launch_bounds__(1024) void k_scan1()
{
    __shared__ int wsum[32];
    int i = blockIdx.x * 1024 + threadIdx.x;
    int v = (i < N_NODES) ? g_cnt[i] : 0;
    int lane = threadIdx.x & 31, w = threadIdx.x >> 5;

    int s = v;
    #pragma unroll
    for (int o = 1; o < 32; o <<= 1) {
        int t = __shfl_up_sync(0xffffffffu, s, o);
        if (lane >= o) s += t;
    }
    if (lane == 31) wsum[w] = s;
    __syncthreads();
    if (w == 0) {
        int t = wsum[lane];
        #pragma unroll
        for (int o = 1; o < 32; o <<= 1) {
            int u = __shfl_up_sync(0xffffffffu, t, o);
            if (lane >= o) t += u;
        }
        wsum[lane] = t;
    }
    __syncthreads();
    int excl = s - v + (w ? wsum[w - 1] : 0);
    if (i < N_NODES) g_off[i] = excl;
    if (threadIdx.x == 1023) g_bsum[blockIdx.x] = wsum[31];
}

__global__ void k_scan2()
{
    __shared__ int sm[128];
    int t = threadIdx.x;
    int v = (t < NB_SCAN) ? g_bsum[t] : 0;
    sm[t] = v;
    __syncthreads();
    for (int o = 1; o < 128; o <<= 1) {
        int u = (t >= o) ? sm[t - o] : 0;
        __syncthreads();
        sm[t] += u;
        __syncthreads();
    }
    if (t < NB_SCAN) g_bsum[t] = sm[t] - v;   // exclusive
    if (t == 127) g_off[N_NODES] = sm[127];
}

__global__ __launch_bounds__(1024) void k_scan3()
{
    int i = blockIdx.x * 1024 + threadIdx.x;
    if (i < N_NODES) {
        int o = g_off[i] + g_bsum[blockIdx.x];
        g_off[i] = o;
        g_cur[i] = o;
    }
}

__global__ void k_scatter(const void* __restrict__ ei)
{
    int e = (blockIdx.x * blockDim.x + threadIdx.x) * 2;
    if (e < N_EDGES) {
        int r0, r1, c0, c1;
        if (g_is64) {
            longlong2 pr = *(const longlong2*)((const long long*)ei + e);
            longlong2 pc = *(const longlong2*)((const long long*)ei + N_EDGES + e);
            r0 = (int)pr.x; r1 = (int)pr.y; c0 = (int)pc.x; c1 = (int)pc.y;
        } else {
            int2 pr = *(const int2*)((const int*)ei + e);
            int2 pc = *(const int2*)((const int*)ei + N_EDGES + e);
            r0 = pr.x; r1 = pr.y; c0 = pc.x; c1 = pc.y;
        }
        if ((unsigned)r0 < N_NODES && (unsigned)c0 < N_NODES) {
            int p = atomicAdd(&g_cur[r0], 1);
            g_src[p] = c0;
        }
        if ((unsigned)r1 < N_NODES && (unsigned)c1 < N_NODES) {
            int p = atomicAdd(&g_cur[r1], 1);
            g_src[p] = c1;
        }
    }
}

// ---------------- per-node online-softmax aggregation -------------
// One warp per destination node; dual edge streams for 2x MLP.
// Q/K fp32 (score precision), V fp16 (linear term).
__global__ __launch_bounds__(256) void k_aggregate(
    const float* __restrict__ D, float* __restrict__ out)
{
    int warp = (blockIdx.x * blockDim.x + threadIdx.x) >> 5;
    int lane = threadIdx.x & 31;
    if (warp >= N_NODES) return;
    const int r = warp;

    const int beg = g_off[r];
    const int end = g_off[r + 1];

    const float4 kv = *(const float4*)&g_K[(size_t)r * OUT_F + lane * 4];
    const float4 Dv = *(const float4*)&D[lane * 4];
    const float scale = 0.1767766952966369f;   // 1/sqrt(32)

    float  m0 = -CUDART_INF_F, sw0 = 0.f;
    float  m1 = -CUDART_INF_F, sw1 = 0.f;
    float4 A0 = make_float4(0.f, 0.f, 0.f, 0.f);
    float4 A1 = make_float4(0.f, 0.f, 0.f, 0.f);

    int e = beg;
    for (; e + 2 <= end; e += 2) {
        const int c0 = g_src[e];
        const int c1 = g_src[e + 1];
        const float4 q0 = *(const float4*)&g_Q[(size_t)c0 * OUT_F + lane * 4];
        const uint2  u0 = *(const uint2*)&g_Vh[(size_t)c0 * OUT_F + lane * 4];
        const float4 q1 = *(const float4*)&g_Q[(size_t)c1 * OUT_F + lane * 4];
        const uint2  u1 = *(const uint2*)&g_Vh[(size_t)c1 * OUT_F + lane * 4];
        const float2 v0a = __half22float2(*(const __half2*)&u0.x);
        const float2 v0b = __half22float2(*(const __half2*)&u0.y);
        const float2 v1a = __half22float2(*(const __half2*)&u1.x);
        const float2 v1b = __half22float2(*(const __half2*)&u1.y);

        float s0, s1;
        {
            float4 t;
            if (c0 == r) {
                t.x = kv.x * Dv.x * q0.x; t.y = kv.y * Dv.y * q0.y;
                t.z = kv.z * Dv.z * q0.z; t.w = kv.w * Dv.w * q0.w;
            } else {
                float dx = kv.x - q0.x, dy = kv.y - q0.y, dz = kv.z - q0.z, dw = kv.w - q0.w;
                t.x = dx * Dv.x * dx; t.y = dy * Dv.y * dy;
                t.z = dz * Dv.z * dz; t.w = dw * Dv.w * dw;
            }
            s0 = t.x + t.y + t.z + t.w;
        }
        {
            float4 t;
            if (c1 == r) {
                t.x = kv.x * Dv.x * q1.x; t.y = kv.y * Dv.y * q1.y;
                t.z = kv.z * Dv.z * q1.z; t.w = kv.w * Dv.w * q1.w;
            } else {
                float dx = kv.x - q1.x, dy = kv.y - q1.y, dz = kv.z - q1.z, dw = kv.w - q1.w;
                t.x = dx * Dv.x * dx; t.y = dy * Dv.y * dy;
                t.z = dz * Dv.z * dz; t.w = dw * Dv.w * dw;
            }
            s1 = t.x + t.y + t.z + t.w;
        }
        s0 += __shfl_xor_sync(0xffffffffu, s0, 1);
        s1 += __shfl_xor_sync(0xffffffffu, s1, 1);
        s0 += __shfl_xor_sync(0xffffffffu, s0, 2);
        s1 += __shfl_xor_sync(0xffffffffu, s1, 2);
        s0 += __shfl_xor_sync(0xffffffffu, s0, 4);
        s1 += __shfl_xor_sync(0xffffffffu, s1, 4);
        s0 *= scale; s1 *= scale;
        s0 = (s0 > 0.f) ? s0 : 0.2f * s0;
        s1 = (s1 > 0.f) ? s1 : 0.2f * s1;

        {
            float mn = fmaxf(m0, s0);
            float cr = __expf(m0 - mn), w = __expf(s0 - mn);
            sw0 = sw0 * cr + w;
            A0.x = A0.x * cr + w * v0a.x; A0.y = A0.y * cr + w * v0a.y;
            A0.z = A0.z * cr + w * v0b.x; A0.w = A0.w * cr + w * v0b.y;
            m0 = mn;
        }
        {
            float mn = fmaxf(m1, s1);
            float cr = __expf(m1 - mn), w = __expf(s1 - mn);
            sw1 = sw1 * cr + w;
            A1.x = A1.x * cr + w * v1a.x; A1.y = A1.y * cr + w * v1a.y;
            A1.z = A1.z * cr + w * v1b.x; A1.w = A1.w * cr + w * v1b.y;
            m1 = mn;
        }
    }
    if (e < end) {
        const int c = g_src[e];
        const float4 q = *(const float4*)&g_Q[(size_t)c * OUT_F + lane * 4];
        const uint2  u = *(const uint2*)&g_Vh[(size_t)c * OUT_F + lane * 4];
        const float2 va = __half22float2(*(const __half2*)&u.x);
        const float2 vb = __half22float2(*(const __half2*)&u.y);
        float4 t;
        if (c == r) {
            t.x = kv.x * Dv.x * q.x; t.y = kv.y * Dv.y * q.y;
            t.z = kv.z * Dv.z * q.z; t.w = kv.w * Dv.w * q.w;
        } else {
            float dx = kv.x - q.x, dy = kv.y - q.y, dz = kv.z - q.z, dw = kv.w - q.w;
            t.x = dx * Dv.x * dx; t.y = dy * Dv.y * dy;
            t.z = dz * Dv.z * dz; t.w = dw * Dv.w * dw;
        }
        float s = t.x + t.y + t.z + t.w;
        s += __shfl_xor_sync(0xffffffffu, s, 1);
        s += __shfl_xor_sync(0xffffffffu, s, 2);
        s += __shfl_xor_sync(0xffffffffu, s, 4);
        s *= scale;
        s = (s > 0.f) ? s : 0.2f * s;
        float mn = fmaxf(m0, s);
        float cr = __expf(m0 - mn), w = __expf(s - mn);
        sw0 = sw0 * cr + w;
        A0.x = A0.x * cr + w * va.x; A0.y = A0.y * cr + w * va.y;
        A0.z = A0.z * cr + w * vb.x; A0.w = A0.w * cr + w * vb.y;
        m0 = mn;
    }

    // merge state1 into state0 (state1 nonempty implies state0 nonempty)
    if (sw1 != 0.f) {
        float mn = fmaxf(m0, m1);
        float c0 = __expf(m0 - mn), c1 = __expf(m1 - mn);
        sw0 = sw0 * c0 + sw1 * c1;
        A0.x = A0.x * c0 + A1.x * c1; A0.y = A0.y * c0 + A1.y * c1;
        A0.z = A0.z * c0 + A1.z * c1; A0.w = A0.w * c0 + A1.w * c1;
    }

    const float inv = 1.f / (sw0 + 1e-16f);
    float4 o = make_float4(A0.x * inv, A0.y * inv, A0.z * inv, A0.w * inv);
    *(float4*)&out[(size_t)r * OUT_F + lane * 4] = o;
}

// ---------------- launch -----------------
extern "C" void kernel_launch(void* const* d_in, const int* in_sizes, int n_in,
                              void* d_out, int out_size)
{
    const float *x = 0, *Wq = 0, *Wk = 0, *Wv = 0, *D = 0;
    const void  *ei = 0;
    int wcount = 0;
    for (int i = 0; i < n_in; i++) {
        long long sz = in_sizes[i];
        if (sz == (long long)N_NODES * IN_F) {
            x = (const float*)d_in[i];
        } else if (sz == (long long)2 * N_EDGES) {
            ei = d_in[i];
        } else if (sz == (long long)IN_F * OUT_F) {
            if (wcount == 0)      Wq = (const float*)d_in[i];
            else if (wcount == 1) Wk = (const float*)d_in[i];
            else                  Wv = (const float*)d_in[i];
            wcount++;
        } else if (sz == OUT_F) {
            D = (const float*)d_in[i];
        }
    }
    float* out = (float*)d_out;

    const int SMEM_DYN = 98304;   // Ah 32K + Al 32K + B 32K
    cudaFuncSetAttribute(qkv_hmma, cudaFuncAttributeMaxDynamicSharedMemorySize, SMEM_DYN);

    k_wconv<<<3, 128>>>(Wq, Wk, Wv);                          // 0
    k_zero<<<(N_NODES + 255) / 256, 256>>>(ei);               // 1
    k_count<<<(N_EDGES / 2 + 255) / 256, 256>>>(ei);          // 2
    qkv_hmma<<<NTILES, 256, SMEM_DYN>>>(x);                   // 3
    k_scan1<<<NB_SCAN, 1024>>>();                             // 4
    k_scan2<<<1, 128>>>();                                    // 5
    k_scan3<<<NB_SCAN, 1024>>>();                             // 6
    k_scatter<<<(N_EDGES / 2 + 255) / 256, 256>>>(ei);        // 7
    k_aggregate<<<(N_NODES * 32 + 255) / 256, 256>>>(D, out); // 8
}

// round 14
// speedup vs baseline: 2.1417x; 1.0317x over previous
#include <cuda_runtime.h>
#include <cuda_fp16.h>
#include <math_constants.h>
#include <cstdint>

#define N_NODES 100000
#define N_EDGES 1600000
#define IN_F    128
#define OUT_F   128     // HEADS * D_K = 4 * 32
#define NB_SCAN ((N_NODES + 1023) / 1024)   // 98
#define NTILES  ((N_NODES + 127) / 128)     // 782

// ---------------- scratch (no allocations allowed) ----------------
__device__ __half g_Qh[N_NODES * OUT_F];    // Q gathered in fp16
__device__ float  g_K[N_NODES * OUT_F];     // K fp32 (read once per node)
__device__ __half g_Vh[N_NODES * OUT_F];    // V gathered in fp16
__device__ int    g_cnt[N_NODES];
__device__ int    g_off[N_NODES + 1];
__device__ int    g_cur[N_NODES];
__device__ int    g_src[N_EDGES];
__device__ int    g_bsum[128];
__device__ int    g_is64;
// single-fp16 weight images, row-major [out_feature][128]
__device__ __half g_Wh[3][OUT_F * IN_F];

// ---------------- mma.sync helpers (base sm_103 legal) ----------------
__device__ __forceinline__ uint32_t smem_u32(const void* p)
{
    uint32_t a;
    asm("{ .reg .u64 t; cvta.to.shared.u64 t, %1; cvt.u32.u64 %0, t; }"
        : "=r"(a) : "l"(p));
    return a;
}
__device__ __forceinline__ void ldsm4(uint32_t& r0, uint32_t& r1, uint32_t& r2,
                                      uint32_t& r3, uint32_t addr)
{
    asm volatile("ldmatrix.sync.aligned.m8n8.x4.shared.b16 {%0,%1,%2,%3}, [%4];"
                 : "=r"(r0), "=r"(r1), "=r"(r2), "=r"(r3) : "r"(addr));
}
__device__ __forceinline__ void mma16816(float* c,
                                         uint32_t a0, uint32_t a1, uint32_t a2, uint32_t a3,
                                         uint32_t b0, uint32_t b1)
{
    asm volatile("mma.sync.aligned.m16n8k16.row.col.f32.f16.f16.f32 "
                 "{%0,%1,%2,%3}, {%4,%5,%6,%7}, {%8,%9}, {%0,%1,%2,%3};"
                 : "+f"(c[0]), "+f"(c[1]), "+f"(c[2]), "+f"(c[3])
                 : "r"(a0), "r"(a1), "r"(a2), "r"(a3), "r"(b0), "r"(b1));
}
// 256B-row swizzled chunk offset: 16 chunks of 16B, low-3 chunk bits XOR row&7
__device__ __forceinline__ uint32_t sw256(int row, int ch)
{
    return (uint32_t)(row << 8) + (uint32_t)(((ch & 8) | ((ch & 7) ^ (row & 7))) << 4);
}

// zero counters + detect edge dtype (thread 0)
__global__ void k_zero(const void* __restrict__ ei)
{
    int i = blockIdx.x * blockDim.x + threadIdx.x;
    if (i < N_NODES) g_cnt[i] = 0;
    if (i == 0) {
        const long long* p = (const long long*)ei;
        bool ok = true;
        #pragma unroll
        for (int k = 0; k < 8; k++) {
            long long v = p[k];
            if (v < 0 || v >= N_NODES) ok = false;
        }
        g_is64 = ok ? 1 : 0;
    }
}

// ---------------- fp16 weight pre-conversion ----------------
__global__ void k_wconv(const float* __restrict__ Wq,
                        const float* __restrict__ Wk,
                        const float* __restrict__ Wv)
{
    int mat = blockIdx.x;
    const float* W = (mat == 0) ? Wq : (mat == 1) ? Wk : Wv;
    int row = threadIdx.x;            // output-feature 0..127
    #pragma unroll 4
    for (int c8 = 0; c8 < 16; c8++) {
        union { __half b[8]; uint4 v; } H;
        #pragma unroll
        for (int j = 0; j < 8; j++)
            H.b[j] = __float2half_rn(W[row * IN_F + c8 * 8 + j]);
        *(uint4*)&g_Wh[mat][row * IN_F + c8 * 8] = H.v;
    }
}

// ---------------- HMMA QKV GEMM ----------------
// grid (NTILES), 256 threads (8 warps, 32x64 warp tiles).
// A = x split into fp16 hi+lo (once per tile, full K in smem, 64KB);
// B = W single fp16 (32KB, reloaded per mat).
// Q,K: 2-term (Ahi+Alo)@B.  V: hi-only (fp16-stored anyway).
__global__ __launch_bounds__(256, 2) void qkv_hmma(const float* __restrict__ xp)
{
    extern __shared__ __align__(1024) unsigned char dsm[];
    const uint32_t sbase = smem_u32(dsm);
    const uint32_t Ah = sbase, Al = sbase + 32768, Bs = sbase + 65536;

    const int tile = blockIdx.x;
    const int tid = threadIdx.x, wid = tid >> 5, lane = tid & 31;
    const int wm = (wid & 3) * 32;        // warp M offset
    const int wn = (wid >> 2) * 64;       // warp N offset

    // ---- A: read x fp32 once, split fp16 hi/lo, store swizzled (full K) ----
    #pragma unroll
    for (int i = tid; i < 2048; i += 256) {
        int row = i >> 4, ch = i & 15;
        uint32_t dst = sw256(row, ch);
        int gr = tile * 128 + row;
        union { __half b[8]; uint4 v; } H, L;
        if (gr < N_NODES) {
            const float4 f0 = *(const float4*)&xp[(size_t)gr * IN_F + ch * 8 + 0];
            const float4 f1 = *(const float4*)&xp[(size_t)gr * IN_F + ch * 8 + 4];
            float fs[8] = {f0.x,f0.y,f0.z,f0.w,f1.x,f1.y,f1.z,f1.w};
            #pragma unroll
            for (int j = 0; j < 8; j++) {
                __half h = __float2half_rn(fs[j]);
                H.b[j] = h;
                L.b[j] = __float2half_rn(fs[j] - __half2float(h));
            }
        } else {
            H.v = make_uint4(0,0,0,0);
            L.v = make_uint4(0,0,0,0);
        }
        *(uint4*)(dsm + (Ah - sbase) + dst) = H.v;
        *(uint4*)(dsm + (Al - sbase) + dst) = L.v;
    }
    __syncthreads();

    for (int mat = 0; mat < 3; mat++) {
        const bool use_lo = (mat != 2);   // V: hi-only
        // ---- B: copy fp16 weights swizzled ----
        const __half* wsrc = g_Wh[mat];
        #pragma unroll
        for (int i = tid; i < 2048; i += 256) {
            int row = i >> 4, ch = i & 15;
            *(uint4*)(dsm + (Bs - sbase) + sw256(row, ch)) =
                *(const uint4*)&wsrc[(size_t)row * IN_F + ch * 8];
        }
        __syncthreads();

        float acc[2][8][4];
        #pragma unroll
        for (int mi = 0; mi < 2; mi++)
            #pragma unroll
            for (int nf = 0; nf < 8; nf++)
                #pragma unroll
                for (int j = 0; j < 4; j++) acc[mi][nf][j] = 0.f;

        #pragma unroll
        for (int k16 = 0; k16 < 8; k16++) {
            const int base8 = (k16 >> 2) << 3;
            const int c3 = ((k16 & 3) << 1) + (lane >> 4);
            uint32_t ah[2][4], al[2][4];
            #pragma unroll
            for (int mi = 0; mi < 2; mi++) {
                int arow = wm + mi * 16 + (lane & 15);
                uint32_t co = (uint32_t)((base8 + (c3 ^ (arow & 7))) << 4) + (uint32_t)(arow << 8);
                ldsm4(ah[mi][0], ah[mi][1], ah[mi][2], ah[mi][3], Ah + co);
                if (use_lo)
                    ldsm4(al[mi][0], al[mi][1], al[mi][2], al[mi][3], Al + co);
            }
            #pragma unroll
            for (int q = 0; q < 4; q++) {
                int brow = wn + q * 16 + (lane & 15);
                uint32_t b0, b1, b2, b3;
                ldsm4(b0, b1, b2, b3,
                      Bs + (uint32_t)(brow << 8) + (uint32_t)((base8 + (c3 ^ (brow & 7))) << 4));
                #pragma unroll
                for (int mi = 0; mi < 2; mi++) {
                    mma16816(acc[mi][q * 2 + 0], ah[mi][0], ah[mi][1], ah[mi][2], ah[mi][3], b0, b2);
                    mma16816(acc[mi][q * 2 + 1], ah[mi][0], ah[mi][1], ah[mi][2], ah[mi][3], b1, b3);
                    if (use_lo) {
                        mma16816(acc[mi][q * 2 + 0], al[mi][0], al[mi][1], al[mi][2], al[mi][3], b0, b2);
                        mma16816(acc[mi][q * 2 + 1], al[mi][0], al[mi][1], al[mi][2], al[mi][3], b1, b3);
                    }
                }
            }
        }
        __syncthreads();   // all MMAs done before B is overwritten next mat

        // ---- epilogue: c0,c1 -> (row t/4, col 2(t%4)); c2,c3 -> row+8 ----
        const int tq = lane >> 2, tr = lane & 3;
        #pragma unroll
        for (int mi = 0; mi < 2; mi++) {
            int r0 = tile * 128 + wm + mi * 16 + tq;
            #pragma unroll
            for (int nf = 0; nf < 8; nf++) {
                int col = wn + nf * 8 + tr * 2;
                if (mat == 1) {
                    if (r0 < N_NODES)
                        *(float2*)&g_K[(size_t)r0 * OUT_F + col] = make_float2(acc[mi][nf][0], acc[mi][nf][1]);
                    if (r0 + 8 < N_NODES)
                        *(float2*)&g_K[(size_t)(r0 + 8) * OUT_F + col] = make_float2(acc[mi][nf][2], acc[mi][nf][3]);
                } else {
                    __half* O = (mat == 0) ? g_Qh : g_Vh;
                    if (r0 < N_NODES)
                        *(__half2*)&O[(size_t)r0 * OUT_F + col] =
                            __floats2half2_rn(acc[mi][nf][0], acc[mi][nf][1]);
                    if (r0 + 8 < N_NODES)
                        *(__half2*)&O[(size_t)(r0 + 8) * OUT_F + col] =
                            __floats2half2_rn(acc[mi][nf][2], acc[mi][nf][3]);
                }
            }
        }
    }
}

// ---------------- CSR build -----------------
// 2 edges per thread, vectorized loads
__global__ void k_count(const void* __restrict__ ei)
{
    int e = (blockIdx.x * blockDim.x + threadIdx.x) * 2;
    if (e < N_EDGES) {
        int r0, r1;
        if (g_is64) {
            longlong2 p = *(const longlong2*)((const long long*)ei + e);
            r0 = (int)p.x; r1 = (int)p.y;
        } else {
            int2 p = *(const int2*)((const int*)ei + e);
            r0 = p.x; r1 = p.y;
        }
        if ((unsigned)r0 < N_NODES) atomicAdd(&g_cnt[r0], 1);
        if ((unsigned)r1 < N_NODES) atomicAdd(&g_cnt[r1], 1);
    }
}

__global__ __launch_bounds__(1024) void k_scan1()
{
    __shared__ int wsum[32];
    int i = blockIdx.x * 1024 + threadIdx.x;
    int v = (i < N_NODES) ? g_cnt[i] : 0;
    int lane = threadIdx.x & 31, w = threadIdx.x >> 5;

    int s = v;
    #pragma unroll
    for (int o = 1; o < 32; o <<= 1) {
        int t = __shfl_up_sync(0xffffffffu, s, o);
        if (lane >= o) s += t;
    }
    if (lane == 31) wsum[w] = s;
    __syncthreads();
    if (w == 0) {
        int t = wsum[lane];
        #pragma unroll
        for (int o = 1; o < 32; o <<= 1) {
            int u = __shfl_up_sync(0xffffffffu, t, o);
            if (lane >= o) t += u;
        }
        wsum[lane] = t;
    }
    __syncthreads();
    int excl = s - v + (w ? wsum[w - 1] : 0);
    if (i < N_NODES) g_off[i] = excl;
    if (threadIdx.x == 1023) g_bsum[blockIdx.x] = wsum[31];
}

__global__ void k_scan2()
{
    __shared__ int sm[128];
    int t = threadIdx.x;
    int v = (t < NB_SCAN) ? g_bsum[t] : 0;
    sm[t] = v;
    __syncthreads();
    for (int o = 1; o < 128; o <<= 1) {
        int u = (t >= o) ? sm[t - o] : 0;
        __syncthreads();
        sm[t] += u;
        __syncthreads();
    }
    if (t < NB_SCAN) g_bsum[t] = sm[t] - v;   // exclusive
    if (t == 127) g_off[N_NODES] = sm[127];
}

__global__ __launch_bounds__(1024) void k_scan3()
{
    int i = blockIdx.x * 1024 + threadIdx.x;
    if (i < N_NODES) {
        int o = g_off[i] + g_bsum[blockIdx.x];
        g_off[i] = o;
        g_cur[i] = o;
    }
}

__global__ void k_scatter(const void* __restrict__ ei)
{
    int e = (blockIdx.x * blockDim.x + threadIdx.x) * 2;
    if (e < N_EDGES) {
        int r0, r1, c0, c1;
        if (g_is64) {
            longlong2 pr = *(const longlong2*)((const long long*)ei + e);
            longlong2 pc = *(const longlong2*)((const long long*)ei + N_EDGES + e);
            r0 = (int)pr.x; r1 = (int)pr.y; c0 = (int)pc.x; c1 = (int)pc.y;
        } else {
            int2 pr = *(const int2*)((const int*)ei + e);
            int2 pc = *(const int2*)((const int*)ei + N_EDGES + e);
            r0 = pr.x; r1 = pr.y; c0 = pc.x; c1 = pc.y;
        }
        if ((unsigned)r0 < N_NODES && (unsigned)c0 < N_NODES) {
            int p = atomicAdd(&g_cur[r0], 1);
            g_src[p] = c0;
        }
        if ((unsigned)r1 < N_NODES && (unsigned)c1 < N_NODES) {
            int p = atomicAdd(&g_cur[r1], 1);
            g_src[p] = c1;
        }
    }
}

// ---------------- per-node online-softmax aggregation -------------
// One warp per destination node; dual edge streams for 2x MLP.
// Q fp16 (gathered), K fp32 (own node), V fp16.
__global__ __launch_bounds__(256) void k_aggregate(
    const float* __restrict__ D, float* __restrict__ out)
{
    int warp = (blockIdx.x * blockDim.x + threadIdx.x) >> 5;
    int lane = threadIdx.x & 31;
    if (warp >= N_NODES) return;
    const int r = warp;

    const int beg = g_off[r];
    const int end = g_off[r + 1];

    const float4 kv = *(const float4*)&g_K[(size_t)r * OUT_F + lane * 4];
    const float4 Dv = *(const float4*)&D[lane * 4];
    const float scale = 0.1767766952966369f;   // 1/sqrt(32)

    float  m0 = -CUDART_INF_F, sw0 = 0.f;
    float  m1 = -CUDART_INF_F, sw1 = 0.f;
    float4 A0 = make_float4(0.f, 0.f, 0.f, 0.f);
    float4 A1 = make_float4(0.f, 0.f, 0.f, 0.f);

    int e = beg;
    for (; e + 2 <= end; e += 2) {
        const int c0 = g_src[e];
        const int c1 = g_src[e + 1];
        const uint2 uq0 = *(const uint2*)&g_Qh[(size_t)c0 * OUT_F + lane * 4];
        const uint2 uv0 = *(const uint2*)&g_Vh[(size_t)c0 * OUT_F + lane * 4];
        const uint2 uq1 = *(const uint2*)&g_Qh[(size_t)c1 * OUT_F + lane * 4];
        const uint2 uv1 = *(const uint2*)&g_Vh[(size_t)c1 * OUT_F + lane * 4];
        const float2 q0a = __half22float2(*(const __half2*)&uq0.x);
        const float2 q0b = __half22float2(*(const __half2*)&uq0.y);
        const float2 q1a = __half22float2(*(const __half2*)&uq1.x);
        const float2 q1b = __half22float2(*(const __half2*)&uq1.y);
        const float2 v0a = __half22float2(*(const __half2*)&uv0.x);
        const float2 v0b = __half22float2(*(const __half2*)&uv0.y);
        const float2 v1a = __half22float2(*(const __half2*)&uv1.x);
        const float2 v1b = __half22float2(*(const __half2*)&uv1.y);

        float s0, s1;
        if (c0 == r) {
            s0 = kv.x * Dv.x * q0a.x + kv.y * Dv.y * q0a.y
               + kv.z * Dv.z * q0b.x + kv.w * Dv.w * q0b.y;
        } else {
            float dx = kv.x - q0a.x, dy = kv.y - q0a.y, dz = kv.z - q0b.x, dw = kv.w - q0b.y;
            s0 = dx * Dv.x * dx + dy * Dv.y * dy + dz * Dv.z * dz + dw * Dv.w * dw;
        }
        if (c1 == r) {
            s1 = kv.x * Dv.x * q1a.x + kv.y * Dv.y * q1a.y
               + kv.z * Dv.z * q1b.x + kv.w * Dv.w * q1b.y;
        } else {
            float dx = kv.x - q1a.x, dy = kv.y - q1a.y, dz = kv.z - q1b.x, dw = kv.w - q1b.y;
            s1 = dx * Dv.x * dx + dy * Dv.y * dy + dz * Dv.z * dz + dw * Dv.w * dw;
        }
        s0 += __shfl_xor_sync(0xffffffffu, s0, 1);
        s1 += __shfl_xor_sync(0xffffffffu, s1, 1);
        s0 += __shfl_xor_sync(0xffffffffu, s0, 2);
        s1 += __shfl_xor_sync(0xffffffffu, s1, 2);
        s0 += __shfl_xor_sync(0xffffffffu, s0, 4);
        s1 += __shfl_xor_sync(0xffffffffu, s1, 4);
        s0 *= scale; s1 *= scale;
        s0 = (s0 > 0.f) ? s0 : 0.2f * s0;
        s1 = (s1 > 0.f) ? s1 : 0.2f * s1;

        {
            float mn = fmaxf(m0, s0);
            float cr = __expf(m0 - mn), w = __expf(s0 - mn);
            sw0 = sw0 * cr + w;
            A0.x = A0.x * cr + w * v0a.x; A0.y = A0.y * cr + w * v0a.y;
            A0.z = A0.z * cr + w * v0b.x; A0.w = A0.w * cr + w * v0b.y;
            m0 = mn;
        }
        {
            float mn = fmaxf(m1, s1);
            float cr = __expf(m1 - mn), w = __expf(s1 - mn);
            sw1 = sw1 * cr + w;
            A1.x = A1.x * cr + w * v1a.x; A1.y = A1.y * cr + w * v1a.y;
            A1.z = A1.z * cr + w * v1b.x; A1.w = A1.w * cr + w * v1b.y;
            m1 = mn;
        }
    }
    if (e < end) {
        const int c = g_src[e];
        const uint2 uq = *(const uint2*)&g_Qh[(size_t)c * OUT_F + lane * 4];
        const uint2 uv = *(const uint2*)&g_Vh[(size_t)c * OUT_F + lane * 4];
        const float2 qa = __half22float2(*(const __half2*)&uq.x);
        const float2 qb = __half22float2(*(const __half2*)&uq.y);
        const float2 va = __half22float2(*(const __half2*)&uv.x);
        const float2 vb = __half22float2(*(const __half2*)&uv.y);
        float s;
        if (c == r) {
            s = kv.x * Dv.x * qa.x + kv.y * Dv.y * qa.y
              + kv.z * Dv.z * qb.x + kv.w * Dv.w * qb.y;
        } else {
            float dx = kv.x - qa.x, dy = kv.y - qa.y, dz = kv.z - qb.x, dw = kv.w - qb.y;
            s = dx * Dv.x * dx + dy * Dv.y * dy + dz * Dv.z * dz + dw * Dv.w * dw;
        }
        s += __shfl_xor_sync(0xffffffffu, s, 1);
        s += __shfl_xor_sync(0xffffffffu, s, 2);
        s += __shfl_xor_sync(0xffffffffu, s, 4);
        s *= scale;
        s = (s > 0.f) ? s : 0.2f * s;
        float mn = fmaxf(m0, s);
        float cr = __expf(m0 - mn), w = __expf(s - mn);
        sw0 = sw0 * cr + w;
        A0.x = A0.x * cr + w * va.x; A0.y = A0.y * cr + w * va.y;
        A0.z = A0.z * cr + w * vb.x; A0.w = A0.w * cr + w * vb.y;
        m0 = mn;
    }

    // merge state1 into state0 (state1 nonempty implies state0 nonempty)
    if (sw1 != 0.f) {
        float mn = fmaxf(m0, m1);
        float c0 = __expf(m0 - mn), c1 = __expf(m1 - mn);
        sw0 = sw0 * c0 + sw1 * c1;
        A0.x = A0.x * c0 + A1.x * c1; A0.y = A0.y * c0 + A1.y * c1;
        A0.z = A0.z * c0 + A1.z * c1; A0.w = A0.w * c0 + A1.w * c1;
    }

    const float inv = 1.f / (sw0 + 1e-16f);
    float4 o = make_float4(A0.x * inv, A0.y * inv, A0.z * inv, A0.w * inv);
    *(float4*)&out[(size_t)r * OUT_F + lane * 4] = o;
}

// ---------------- launch -----------------
extern "C" void kernel_launch(void* const* d_in, const int* in_sizes, int n_in,
                              void* d_out, int out_size)
{
    const float *x = 0, *Wq = 0, *Wk = 0, *Wv = 0, *D = 0;
    const void  *ei = 0;
    int wcount = 0;
    for (int i = 0; i < n_in; i++) {
        long long sz = in_sizes[i];
        if (sz == (long long)N_NODES * IN_F) {
            x = (const float*)d_in[i];
        } else if (sz == (long long)2 * N_EDGES) {
            ei = d_in[i];
        } else if (sz == (long long)IN_F * OUT_F) {
            if (wcount == 0)      Wq = (const float*)d_in[i];
            else if (wcount == 1) Wk = (const float*)d_in[i];
            else                  Wv = (const float*)d_in[i];
            wcount++;
        } else if (sz == OUT_F) {
            D = (const float*)d_in[i];
        }
    }
    float* out = (float*)d_out;

    const int SMEM_DYN = 98304;   // Ah 32K + Al 32K + B 32K
    cudaFuncSetAttribute(qkv_hmma, cudaFuncAttributeMaxDynamicSharedMemorySize, SMEM_DYN);

    k_wconv<<<3, 128>>>(Wq, Wk, Wv);                          // 0
    k_zero<<<(N_NODES + 255) / 256, 256>>>(ei);               // 1
    k_count<<<(N_EDGES / 2 + 255) / 256, 256>>>(ei);          // 2
    qkv_hmma<<<NTILES, 256, SMEM_DYN>>>(x);                   // 3
    k_scan1<<<NB_SCAN, 1024>>>();                             // 4
    k_scan2<<<1, 128>>>();                                    // 5
    k_scan3<<<NB_SCAN, 1024>>>();                             // 6
    k_scatter<<<(N_EDGES / 2 + 255) / 256, 256>>>(ei);        // 7
    k_aggregate<<<(N_NODES * 32 + 255) / 256, 256>>>(D, out); // 8
}